// round 13
// baseline (speedup 1.0000x reference)
#include <cuda_runtime.h>
#include <cuda_fp16.h>
#include <math.h>
#include <stdint.h>

// Problem constants
#define Bsz 2
#define Tn 4096
#define Dm 2048
#define Hh 8
#define DK 128
#define DV 256
#define Wc 4
#define BH (Bsz*Hh)          // 16
#define QKC (Hh*DK)          // 1024
#define VC  (Hh*DV)          // 2048
#define NPRE 6144            // packed q|k|v|g columns

// ---------------- scratch (device globals; no allocations allowed) -------------
__device__ float   g_pre [(size_t)Bsz*Tn*NPRE];   // packed projections (fp32)
__device__ __half2 g_Wch [(size_t)(Dm/2)*NPRE];   // packed weights, half2 pairs along K
__device__ __half2 g_Woh [(size_t)(Dm/2)*Dm];     // Wo, half2 pairs along K
__device__ __half2 g_xh  [(size_t)Bsz*Tn*(Dm/2)]; // x, half2 pairs along K
__device__ __half2 g_onh [(size_t)Bsz*Tn*(VC/2)]; // gated-norm output, half2 pairs
__device__ float   g_qn  [(size_t)BH*Tn*DK];
__device__ float   g_kn  [(size_t)BH*Tn*DK];
__device__ float   g_vc  [(size_t)BH*Tn*DV];
__device__ float   g_eg  [(size_t)BH*Tn];
__device__ float   g_beta[(size_t)BH*Tn];
__device__ float   g_kk  [(size_t)BH*Tn];         // c_t = k_{t+1} . k_t
__device__ float   g_o   [(size_t)BH*Tn*DV];

__device__ __forceinline__ float siluf(float x) { return x / (1.f + __expf(-x)); }

__device__ __forceinline__ uint32_t smem_u32(const void* p) {
    uint32_t a;
    asm("{ .reg .u64 t; cvta.to.shared.u64 t, %1; cvt.u32.u64 %0, t; }" : "=r"(a) : "l"(p));
    return a;
}

#define CP_ASYNC16(dst, src) \
    asm volatile("cp.async.cg.shared.global [%0], [%1], 16;" \
        :: "r"((uint32_t)(dst)), "l"(src) : "memory")
#define CP_COMMIT() asm volatile("cp.async.commit_group;" ::: "memory")

// ============ fp16 m16n8k16 GEMM, fp32 accum, 4-stage cp.async pipeline ========
#define TM 128
#define TN 128
#define TKc2 16
#define AST2 20
#define BST2 136
#define STG_WORDS (TM*AST2 + TKc2*BST2)    // 4736
#define NST 4
#define SMEM_GEMMH (NST*STG_WORDS*4)       // 75776 bytes

__global__ void __launch_bounds__(128, 2) gemm_h(
    const __half2* __restrict__ A, const __half2* __restrict__ B,
    float* __restrict__ C, int Mtot, int Ntot, int K2tot) {
    extern __shared__ uint32_t sm[];
    const int tid = threadIdx.x, lane = tid & 31, wid = tid >> 5;
    const int wm = (wid & 1) * 64;
    const int wn = (wid >> 1) * 64;
    const int m0 = blockIdx.y * TM, n0 = blockIdx.x * TN;
    const int la3 = lane & 3, l4 = lane >> 2;

    float acc[4][8][4];
#pragma unroll
    for (int mt = 0; mt < 4; mt++)
#pragma unroll
        for (int nt = 0; nt < 8; nt++)
#pragma unroll
            for (int i = 0; i < 4; i++) acc[mt][nt][i] = 0.f;

    const int nch = K2tot / TKc2;

    auto load_stage = [&](int c, int s) {
        uint32_t* sa = sm + s * STG_WORDS;
        uint32_t* sb = sa + TM * AST2;
        const __half2* Ab = A + (size_t)m0 * K2tot + c * TKc2;
        const __half2* Bb = B + (size_t)(c * TKc2) * Ntot + n0;
#pragma unroll
        for (int i = 0; i < 4; i++) {
            int idx = tid + i * 128;
            int r = idx >> 2, cc = idx & 3;
            CP_ASYNC16(smem_u32(sa + r * AST2 + cc * 4), Ab + (size_t)r * K2tot + cc * 4);
        }
#pragma unroll
        for (int i = 0; i < 4; i++) {
            int idx = tid + i * 128;
            int r = idx >> 5, n4 = idx & 31;
            CP_ASYNC16(smem_u32(sb + r * BST2 + n4 * 4), Bb + (size_t)r * Ntot + n4 * 4);
        }
        CP_COMMIT();
    };

    load_stage(0, 0);
    load_stage(1, 1);
    load_stage(2, 2);

    for (int c = 0; c < nch; c++) {
        if (c + 3 <= nch)      asm volatile("cp.async.wait_group 2;" ::: "memory");
        else if (c + 2 == nch) asm volatile("cp.async.wait_group 1;" ::: "memory");
        else                   asm volatile("cp.async.wait_group 0;" ::: "memory");
        __syncthreads();
        if (c + 3 < nch) load_stage(c + 3, (c + 3) % NST);

        const uint32_t* sa = sm + (c % NST) * STG_WORDS;
        const uint32_t* sb = sa + TM * AST2;
#pragma unroll
        for (int ks = 0; ks < 2; ks++) {
            uint32_t a[4][4];
#pragma unroll
            for (int mt = 0; mt < 4; mt++) {
                int mm = wm + mt * 16 + l4;
                int base = mm * AST2 + ks * 8 + la3;
                a[mt][0] = sa[base];
                a[mt][1] = sa[base + 8 * AST2];
                a[mt][2] = sa[base + 4];
                a[mt][3] = sa[base + 8 * AST2 + 4];
            }
            uint32_t b[8][2];
#pragma unroll
            for (int nt = 0; nt < 8; nt++) {
                int nn = wn + nt * 8 + l4;
                b[nt][0] = sb[(ks * 8 + la3) * BST2 + nn];
                b[nt][1] = sb[(ks * 8 + la3 + 4) * BST2 + nn];
            }
#pragma unroll
            for (int mt = 0; mt < 4; mt++)
#pragma unroll
                for (int nt = 0; nt < 8; nt++) {
                    asm volatile(
                        "mma.sync.aligned.m16n8k16.row.col.f32.f16.f16.f32 "
                        "{%0,%1,%2,%3}, {%4,%5,%6,%7}, {%8,%9}, {%0,%1,%2,%3};"
                        : "+f"(acc[mt][nt][0]), "+f"(acc[mt][nt][1]),
                          "+f"(acc[mt][nt][2]), "+f"(acc[mt][nt][3])
                        : "r"(a[mt][0]), "r"(a[mt][1]), "r"(a[mt][2]), "r"(a[mt][3]),
                          "r"(b[nt][0]), "r"(b[nt][1]));
                }
        }
    }

#pragma unroll
    for (int mt = 0; mt < 4; mt++) {
#pragma unroll
        for (int nt = 0; nt < 8; nt++) {
            int row = m0 + wm + mt * 16 + l4;
            int col = n0 + wn + nt * 8 + la3 * 2;
            *reinterpret_cast<float2*>(&C[(size_t)row * Ntot + col]) =
                make_float2(acc[mt][nt][0], acc[mt][nt][1]);
            *reinterpret_cast<float2*>(&C[(size_t)(row + 8) * Ntot + col]) =
                make_float2(acc[mt][nt][2], acc[mt][nt][3]);
        }
    }
}

// ---------------- pack Wq|Wk|Wv|Wg -> g_Wch [K/2][6144] half2 -------------------
__global__ void pack_w_kernel(const float* __restrict__ Wq, const float* __restrict__ Wk,
                              const float* __restrict__ Wv, const float* __restrict__ Wg) {
    size_t n = (size_t)(Dm / 2) * NPRE;
    for (size_t i = (size_t)blockIdx.x * blockDim.x + threadIdx.x; i < n;
         i += (size_t)gridDim.x * blockDim.x) {
        int col = (int)(i % NPRE);
        int k2 = (int)(i / NPRE);
        const float* src; int c;
        if (col < 1024)       { src = Wq; c = col;        }
        else if (col < 2048)  { src = Wk; c = col - 1024; }
        else if (col < 4096)  { src = Wv; c = col - 2048; }
        else                  { src = Wg; c = col - 4096; }
        int ncol = (col < 2048) ? 1024 : 2048;
        float v0 = src[(size_t)(2 * k2) * ncol + c];
        float v1 = src[(size_t)(2 * k2 + 1) * ncol + c];
        g_Wch[i] = __floats2half2_rn(v0, v1);
    }
}

__global__ void pack_wo_kernel(const float* __restrict__ Wo) {
    size_t n = (size_t)(Dm / 2) * Dm;
    for (size_t i = (size_t)blockIdx.x * blockDim.x + threadIdx.x; i < n;
         i += (size_t)gridDim.x * blockDim.x) {
        int col = (int)(i % Dm);
        int k2 = (int)(i / Dm);
        float v0 = Wo[(size_t)(2 * k2) * Dm + col];
        float v1 = Wo[(size_t)(2 * k2 + 1) * Dm + col];
        g_Woh[i] = __floats2half2_rn(v0, v1);
    }
}

__global__ void pack_x_kernel(const float* __restrict__ x) {
    size_t n = (size_t)Bsz * Tn * Dm / 2;
    for (size_t i = (size_t)blockIdx.x * blockDim.x + threadIdx.x; i < n;
         i += (size_t)gridDim.x * blockDim.x) {
        float2 v = reinterpret_cast<const float2*>(x)[i];
        g_xh[i] = __floats2half2_rn(v.x, v.y);
    }
}

// ---------------- fused beta/g projection + activations ------------------------
__global__ void betag_fused_kernel(const float* __restrict__ x,
                                   const float* __restrict__ Wb, const float* __restrict__ Wa,
                                   const float* __restrict__ A_log,
                                   const float* __restrict__ dt_bias) {
    int wid = threadIdx.x >> 5, lane = threadIdx.x & 31;
    int row = blockIdx.x * 8 + wid;
    if (row >= Bsz * Tn) return;
    const float* xr = x + (size_t)row * Dm;
    float accB[8], accA[8];
#pragma unroll
    for (int h = 0; h < 8; h++) { accB[h] = 0.f; accA[h] = 0.f; }
    for (int k = lane; k < Dm; k += 32) {
        float xv = xr[k];
        const float4* wb = reinterpret_cast<const float4*>(Wb + (size_t)k * 8);
        const float4* wa = reinterpret_cast<const float4*>(Wa + (size_t)k * 8);
        float4 b0 = wb[0], b1 = wb[1], a0 = wa[0], a1 = wa[1];
        accB[0] += xv * b0.x; accB[1] += xv * b0.y; accB[2] += xv * b0.z; accB[3] += xv * b0.w;
        accB[4] += xv * b1.x; accB[5] += xv * b1.y; accB[6] += xv * b1.z; accB[7] += xv * b1.w;
        accA[0] += xv * a0.x; accA[1] += xv * a0.y; accA[2] += xv * a0.z; accA[3] += xv * a0.w;
        accA[4] += xv * a1.x; accA[5] += xv * a1.y; accA[6] += xv * a1.z; accA[7] += xv * a1.w;
    }
#pragma unroll
    for (int h = 0; h < 8; h++) {
#pragma unroll
        for (int m = 16; m; m >>= 1) {
            accB[h] += __shfl_xor_sync(0xffffffffu, accB[h], m);
            accA[h] += __shfl_xor_sync(0xffffffffu, accA[h], m);
        }
    }
    if (lane < 8) {
        int h = lane;
        float beta = 1.f / (1.f + expf(-accB[h]));
        float xg = accA[h] + dt_bias[h];
        float sp = (xg > 20.f) ? xg : log1pf(expf(xg));
        float gg = -expf(A_log[h]) * sp;
        int b = row / Tn, t = row % Tn;
        size_t o = (size_t)(b * Hh + h) * Tn + t;
        g_eg[o] = expf(gg);
        g_beta[o] = beta;
    }
}

// ---------------- causal dwconv + silu + l2norm for q/k (4 t's per block) ------
__global__ void convnorm_qk4_kernel(const float* __restrict__ convw,
                                    float* __restrict__ out, int off, float scale) {
    int h  = blockIdx.x & 7;
    int tq = (blockIdx.x >> 3) & (Tn / 4 - 1);
    int b  = blockIdx.x >> (3 + 10);
    int t0 = tq * 4;
    int c  = h * DK + threadIdx.x;

    const float* base = g_pre + (size_t)b * Tn * NPRE + off + c;
    float w0 = convw[(size_t)c * Wc + 0];
    float w1 = convw[(size_t)c * Wc + 1];
    float w2 = convw[(size_t)c * Wc + 2];
    float w3 = convw[(size_t)c * Wc + 3];

    float r[7];
#pragma unroll
    for (int i = 0; i < 7; i++) {
        int tt = t0 - 3 + i;
        r[i] = (tt >= 0) ? base[(size_t)tt * NPRE] : 0.f;
    }
    float s[4], ss[4];
#pragma unroll
    for (int j = 0; j < 4; j++) {
        float a = r[j] * w0 + r[j + 1] * w1 + r[j + 2] * w2 + r[j + 3] * w3;
        s[j] = siluf(a);
        ss[j] = s[j] * s[j];
    }
#pragma unroll
    for (int m = 16; m; m >>= 1) {
#pragma unroll
        for (int j = 0; j < 4; j++)
            ss[j] += __shfl_xor_sync(0xffffffffu, ss[j], m);
    }
    __shared__ float wsum[4][4];
    if ((threadIdx.x & 31) == 0) {
        int wd = threadIdx.x >> 5;
#pragma unroll
        for (int j = 0; j < 4; j++) wsum[wd][j] = ss[j];
    }
    __syncthreads();
    size_t ob = ((size_t)(b * Hh + h) * Tn + t0) * DK + threadIdx.x;
#pragma unroll
    for (int j = 0; j < 4; j++) {
        float tot = wsum[0][j] + wsum[1][j] + wsum[2][j] + wsum[3][j];
        out[ob + (size_t)j * DK] = s[j] * rsqrtf(tot + 1e-6f) * scale;
    }
}

// ---------------- causal dwconv + silu for v (4 t's per thread) -----------------
__global__ void convsilu_v4_kernel(const float* __restrict__ convw) {
    size_t total = (size_t)Bsz * (Tn / 4) * VC;
    for (size_t idx = (size_t)blockIdx.x * blockDim.x + threadIdx.x;
         idx < total; idx += (size_t)gridDim.x * blockDim.x) {
        int c  = (int)(idx % VC);
        int tq = (int)((idx / VC) % (Tn / 4));
        int b  = (int)(idx / ((size_t)VC * (Tn / 4)));
        int t0 = tq * 4;
        int h = c >> 8, dv = c & 255;

        const float* base = g_pre + (size_t)b * Tn * NPRE + 2048 + c;
        float w0 = convw[(size_t)c * Wc + 0];
        float w1 = convw[(size_t)c * Wc + 1];
        float w2 = convw[(size_t)c * Wc + 2];
        float w3 = convw[(size_t)c * Wc + 3];

        float r[7];
#pragma unroll
        for (int i = 0; i < 7; i++) {
            int tt = t0 - 3 + i;
            r[i] = (tt >= 0) ? base[(size_t)tt * NPRE] : 0.f;
        }
        size_t ob = ((size_t)(b * Hh + h) * Tn + t0) * DV + dv;
#pragma unroll
        for (int j = 0; j < 4; j++) {
            float a = r[j] * w0 + r[j + 1] * w1 + r[j + 2] * w2 + r[j + 3] * w3;
            g_vc[ob + (size_t)j * DV] = siluf(a);
        }
    }
}

// ---------------- k_{t+1} . k_t dots --------------------------------------------
__global__ void kk_kernel() {
    int wid = threadIdx.x >> 5, lane = threadIdx.x & 31;
    int idx = blockIdx.x * 8 + wid;              // bh*Tn + t
    if (idx >= BH * Tn) return;
    int t = idx & (Tn - 1);
    float s = 0.f;
    if (t + 1 < Tn) {
        const float* k0 = g_kn + (size_t)idx * DK;
        float4 a = reinterpret_cast<const float4*>(k0)[lane];
        float4 b = reinterpret_cast<const float4*>(k0 + DK)[lane];
        s = a.x * b.x + a.y * b.y + a.z * b.z + a.w * b.w;
    }
#pragma unroll
    for (int m = 16; m; m >>= 1) s += __shfl_xor_sync(0xffffffffu, s, m);
    if (lane == 0) g_kk[idx] = s;
}

// ---------------- gated delta-rule recurrence (512 thr, 4 warps/SMSP) -----------
// warp = 2 cols x 16 subs (8 rows each); col = (wid<<1)|(lane>>4), sub = lane&15.
// E-pipelined (p_{t+1} = eg_t*E_t + c_t*w_t); o deferred to padded smem buffer.
#define DVT 32
#define STAGE 32
#define SUBR 12                    // 8 data + 4 pad words per sub-run (48B aligned)
#define SKROW 192                  // 16*SUBR
#define OPS 544                    // oP row stride (32 cols x 17)
#define OFF_SK 0
#define OFF_SQ (OFF_SK + (STAGE+1)*SKROW)   // 6336
#define OFF_SV (OFF_SQ + STAGE*SKROW)       // 12480
#define OFF_OP (OFF_SV + STAGE*DVT)         // 13504
#define OFF_EG (OFF_OP + STAGE*OPS)         // 30912
#define OFF_BT (OFF_EG + STAGE)
#define OFF_CC (OFF_BT + STAGE)
#define DELTA_SMEM ((OFF_CC + STAGE) * 4)   // 124032 bytes

__global__ void __launch_bounds__(512, 1) delta_kernel() {
    extern __shared__ float dsm[];
    float* sK  = dsm + OFF_SK;
    float* sQ  = dsm + OFF_SQ;
    float* sV  = dsm + OFF_SV;
    float* oP  = dsm + OFF_OP;
    float* sEg = dsm + OFF_EG;
    float* sBt = dsm + OFF_BT;
    float* sC  = dsm + OFF_CC;

    int bh = blockIdx.x;
    int vt = blockIdx.y;
    int tid = threadIdx.x;             // 512
    int wid = tid >> 5, lane = tid & 31;
    int col = (wid << 1) | (lane >> 4);  // 0..31
    int sub = lane & 15;                 // rows [sub*8, sub*8+8)

    const float* kb  = g_kn   + (size_t)bh * Tn * DK;
    const float* qb  = g_qn   + (size_t)bh * Tn * DK;
    const float* vb  = g_vc   + (size_t)bh * Tn * DV;
    const float* egb = g_eg   + (size_t)bh * Tn;
    const float* btb = g_beta + (size_t)bh * Tn;
    const float* ccb = g_kk   + (size_t)bh * Tn;
    float* ob        = g_o    + (size_t)bh * Tn * DV;

    float S[8];
#pragma unroll
    for (int i = 0; i < 8; i++) S[i] = 0.f;
    float E_prev = 0.f, w_prev = 0.f, c_prev = 0.f, eg_prev = 0.f;

    for (int c0 = 0; c0 < Tn; c0 += STAGE) {
        __syncthreads();
        // K rows 0..32 (33), Q rows 0..31: 32 rows x 32 float4 each
#pragma unroll
        for (int l = 0; l < 2; l++) {
            int linear = tid + l * 512;
            int tl = linear >> 5;
            int v4 = linear & 31;
            float4 kv = reinterpret_cast<const float4*>(kb + (size_t)(c0 + tl) * DK)[v4];
            float4 qv = reinterpret_cast<const float4*>(qb + (size_t)(c0 + tl) * DK)[v4];
            int off = (v4 >> 1) * SUBR + (v4 & 1) * 4;
            *reinterpret_cast<float4*>(&sK[tl * SKROW + off]) = kv;
            *reinterpret_cast<float4*>(&sQ[tl * SKROW + off]) = qv;
        }
        if (tid < 32) {
            int row = c0 + 32; if (row > Tn - 1) row = Tn - 1;
            float4 kv = reinterpret_cast<const float4*>(kb + (size_t)row * DK)[tid];
            int off = (tid >> 1) * SUBR + (tid & 1) * 4;
            *reinterpret_cast<float4*>(&sK[32 * SKROW + off]) = kv;
        }
        if (tid < 256) {
            int tl = tid >> 3;
            int v4 = tid & 7;
            float4 vv = reinterpret_cast<const float4*>(vb + (size_t)(c0 + tl) * DV + vt * DVT)[v4];
            *reinterpret_cast<float4*>(&sV[tl * DVT + v4 * 4]) = vv;
        }
        if (tid < STAGE) {
            sEg[tid] = egb[c0 + tid];
            sBt[tid] = btb[c0 + tid];
            sC[tid]  = ccb[c0 + tid];
        }
        __syncthreads();

        float4 kq0, kq1;
        {
            const float4* kr = reinterpret_cast<const float4*>(&sK[sub * SUBR]);
            kq0 = kr[0]; kq1 = kr[1];
        }

#pragma unroll 8
        for (int s = 0; s < STAGE; s++) {
            float eg = sEg[s], bt = sBt[s], cc = sC[s];
            float v = sV[s * DVT + col];

            // scalar recurrence: p_t = eg_{t-1}*E_{t-1} + c_{t-1}*w_{t-1}
            float p = eg_prev * E_prev + c_prev * w_prev;
            float w = bt * (v - eg * p);

            // k_{t+1}
            float4 kn0, kn1;
            {
                const float4* krn =
                    reinterpret_cast<const float4*>(&sK[(s + 1) * SKROW + sub * SUBR]);
                kn0 = krn[0]; kn1 = krn[1];
            }

            // E_t = k_{t+1} . S_{t-1} (pre-update), 2 chains
            float e0 = kn0.x * S[0] + kn0.z * S[2] + kn1.x * S[4] + kn1.z * S[6];
            float e1 = kn0.y * S[1] + kn0.w * S[3] + kn1.y * S[5] + kn1.w * S[7];
            float E = e0 + e1;
            E += __shfl_xor_sync(0xffffffffu, E, 1);
            E += __shfl_xor_sync(0xffffffffu, E, 2);
            E += __shfl_xor_sync(0xffffffffu, E, 4);
            E += __shfl_xor_sync(0xffffffffu, E, 8);

            // S = eg*S + k*w ; o partial = q . S_new (deferred reduction)
            const float4* qr = reinterpret_cast<const float4*>(&sQ[s * SKROW + sub * SUBR]);
            float4 q0 = qr[0], q1 = qr[1];
            S[0] = eg * S[0] + kq0.x * w;
            S[1] = eg * S[1] + kq0.y * w;
            S[2] = eg * S[2] + kq0.z * w;
            S[3] = eg * S[3] + kq0.w * w;
            float o0 = q0.x * S[0] + q0.z * S[2];
            float o1 = q0.y * S[1] + q0.w * S[3];
            S[4] = eg * S[4] + kq1.x * w;
            S[5] = eg * S[5] + kq1.y * w;
            S[6] = eg * S[6] + kq1.z * w;
            S[7] = eg * S[7] + kq1.w * w;
            o0 += q1.x * S[4] + q1.z * S[6];
            o1 += q1.y * S[5] + q1.w * S[7];
            oP[s * OPS + col * 17 + sub] = o0 + o1;

            E_prev = E; w_prev = w; c_prev = cc; eg_prev = eg;
            kq0 = kn0; kq1 = kn1;
        }
        __syncthreads();

        // batched o reduction + store: 1024 outputs, 2 per thread
#pragma unroll
        for (int r = 0; r < 2; r++) {
            int idx = r * 512 + tid;
            int t = idx >> 5, cl = idx & 31;
            const float* b = &oP[t * OPS + cl * 17];
            float sum = (((b[0] + b[1]) + (b[2] + b[3])) + ((b[4] + b[5]) + (b[6] + b[7])))
                      + (((b[8] + b[9]) + (b[10] + b[11])) + ((b[12] + b[13]) + (b[14] + b[15])));
            ob[(size_t)(c0 + t) * DV + vt * DVT + cl] = sum;
        }
    }
}

// ---------------- gated RMSNorm + silu(gate), half2 output ---------------------
__global__ void gatednorm_kernel(const float* __restrict__ g_norm_w) {
    int idx = blockIdx.x;
    int h = idx % Hh;
    int t = (idx / Hh) % Tn;
    int b = idx / (Hh * Tn);
    int dv = threadIdx.x * 2;
    size_t obase = ((size_t)(b * Hh + h) * Tn + t) * DV;
    float o0 = g_o[obase + dv];
    float o1 = g_o[obase + dv + 1];
    float ss = o0 * o0 + o1 * o1;
#pragma unroll
    for (int m = 16; m; m >>= 1) ss += __shfl_xor_sync(0xffffffffu, ss, m);
    __shared__ float wsum[4];
    if ((threadIdx.x & 31) == 0) wsum[threadIdx.x >> 5] = ss;
    __syncthreads();
    float tot = wsum[0] + wsum[1] + wsum[2] + wsum[3];
    float r = rsqrtf(tot * (1.f / DV) + 1e-5f);
    size_t gb = ((size_t)(b * Tn + t)) * NPRE + 4096 + h * DV + dv;
    float gt0 = g_pre[gb], gt1 = g_pre[gb + 1];
    float v0 = o0 * r * g_norm_w[dv] * siluf(gt0);
    float v1 = o1 * r * g_norm_w[dv + 1] * siluf(gt1);
    g_onh[((size_t)(b * Tn + t)) * (VC / 2) + (h * DV + dv) / 2] = __floats2half2_rn(v0, v1);
}

// ---------------- launch --------------------------------------------------------
extern "C" void kernel_launch(void* const* d_in, const int* in_sizes, int n_in,
                              void* d_out, int out_size) {
    const float* x       = (const float*)d_in[0];
    const float* Wq      = (const float*)d_in[1];
    const float* Wk      = (const float*)d_in[2];
    const float* Wv      = (const float*)d_in[3];
    const float* Wb      = (const float*)d_in[4];
    const float* Wa      = (const float*)d_in[5];
    const float* Wg      = (const float*)d_in[6];
    const float* Wo      = (const float*)d_in[7];
    const float* conv_q  = (const float*)d_in[8];
    const float* conv_k  = (const float*)d_in[9];
    const float* conv_v  = (const float*)d_in[10];
    const float* A_log   = (const float*)d_in[11];
    const float* dt_bias = (const float*)d_in[12];
    const float* gnw     = (const float*)d_in[13];
    float* out = (float*)d_out;

    float *pre, *qn, *kn;
    __half2 *Wch, *Woh, *xh, *onh;
    cudaGetSymbolAddress((void**)&pre, g_pre);
    cudaGetSymbolAddress((void**)&Wch, g_Wch);
    cudaGetSymbolAddress((void**)&Woh, g_Woh);
    cudaGetSymbolAddress((void**)&xh,  g_xh);
    cudaGetSymbolAddress((void**)&onh, g_onh);
    cudaGetSymbolAddress((void**)&qn,  g_qn);
    cudaGetSymbolAddress((void**)&kn,  g_kn);

    cudaFuncSetAttribute(gemm_h, cudaFuncAttributeMaxDynamicSharedMemorySize, SMEM_GEMMH);
    cudaFuncSetAttribute(delta_kernel, cudaFuncAttributeMaxDynamicSharedMemorySize, DELTA_SMEM);

    const int M = Bsz * Tn;   // 8192

    pack_w_kernel<<<1024, 256>>>(Wq, Wk, Wv, Wg);
    pack_wo_kernel<<<512, 256>>>(Wo);
    pack_x_kernel<<<1024, 256>>>(x);

    // big projection GEMM: pre[8192,6144] = xh @ Wch
    gemm_h<<<dim3(NPRE / TN, M / TM), 128, SMEM_GEMMH>>>(xh, Wch, pre, M, NPRE, Dm / 2);

    betag_fused_kernel<<<M / 8, 256>>>(x, Wb, Wa, A_log, dt_bias);

    convnorm_qk4_kernel<<<Bsz * (Tn / 4) * Hh, DK>>>(conv_q, qn, 0, 0.08838834764831845f);
    convnorm_qk4_kernel<<<Bsz * (Tn / 4) * Hh, DK>>>(conv_k, kn, 1024, 1.0f);
    convsilu_v4_kernel<<<4096, 256>>>(conv_v);

    kk_kernel<<<BH * Tn / 8, 256>>>();

    {
        dim3 grid(BH, DV / DVT);
        delta_kernel<<<grid, 512, DELTA_SMEM>>>();
    }

    gatednorm_kernel<<<Bsz * Tn * Hh, DV / 2>>>(gnw);

    // output GEMM: out[8192,2048] = onh @ Woh
    gemm_h<<<dim3(Dm / TN, M / TM), 128, SMEM_GEMMH>>>(onh, Woh, out, M, Dm, Dm / 2);
}

// round 14
// speedup vs baseline: 1.0941x; 1.0941x over previous
#include <cuda_runtime.h>
#include <cuda_fp16.h>
#include <math.h>
#include <stdint.h>

// Problem constants
#define Bsz 2
#define Tn 4096
#define Dm 2048
#define Hh 8
#define DK 128
#define DV 256
#define Wc 4
#define BH (Bsz*Hh)          // 16
#define QKC (Hh*DK)          // 1024
#define VC  (Hh*DV)          // 2048
#define NPRE 6144            // packed q|k|v|g columns

// ---------------- scratch (device globals; no allocations allowed) -------------
__device__ float   g_pre [(size_t)Bsz*Tn*NPRE];   // packed projections (fp32)
__device__ __half2 g_Wch [(size_t)(Dm/2)*NPRE];   // packed weights, half2 pairs along K
__device__ __half2 g_Woh [(size_t)(Dm/2)*Dm];     // Wo, half2 pairs along K
__device__ __half2 g_xh  [(size_t)Bsz*Tn*(Dm/2)]; // x, half2 pairs along K
__device__ __half2 g_onh [(size_t)Bsz*Tn*(VC/2)]; // gated-norm output, half2 pairs
__device__ float   g_qn  [(size_t)BH*Tn*DK];
__device__ float   g_kn  [(size_t)BH*Tn*DK];
__device__ float   g_vc  [(size_t)BH*Tn*DV];
__device__ float   g_eg  [(size_t)BH*Tn];
__device__ float   g_beta[(size_t)BH*Tn];
__device__ float   g_kk  [(size_t)BH*Tn];         // c_t = k_{t+1} . k_t
__device__ float   g_o   [(size_t)BH*Tn*DV];

__device__ __forceinline__ float siluf(float x) { return x / (1.f + __expf(-x)); }

__device__ __forceinline__ uint32_t smem_u32(const void* p) {
    uint32_t a;
    asm("{ .reg .u64 t; cvta.to.shared.u64 t, %1; cvt.u32.u64 %0, t; }" : "=r"(a) : "l"(p));
    return a;
}

#define CP_ASYNC16(dst, src) \
    asm volatile("cp.async.cg.shared.global [%0], [%1], 16;" \
        :: "r"((uint32_t)(dst)), "l"(src) : "memory")
#define CP_COMMIT() asm volatile("cp.async.commit_group;" ::: "memory")

// ============ fp16 m16n8k16 GEMM, fp32 accum, 4-stage cp.async pipeline ========
#define TM 128
#define TN 128
#define TKc2 16
#define AST2 20
#define BST2 136
#define STG_WORDS (TM*AST2 + TKc2*BST2)    // 4736
#define NST 4
#define SMEM_GEMMH (NST*STG_WORDS*4)       // 75776 bytes

__global__ void __launch_bounds__(128, 2) gemm_h(
    const __half2* __restrict__ A, const __half2* __restrict__ B,
    float* __restrict__ C, int Mtot, int Ntot, int K2tot) {
    extern __shared__ uint32_t sm[];
    const int tid = threadIdx.x, lane = tid & 31, wid = tid >> 5;
    const int wm = (wid & 1) * 64;
    const int wn = (wid >> 1) * 64;
    const int m0 = blockIdx.y * TM, n0 = blockIdx.x * TN;
    const int la3 = lane & 3, l4 = lane >> 2;

    float acc[4][8][4];
#pragma unroll
    for (int mt = 0; mt < 4; mt++)
#pragma unroll
        for (int nt = 0; nt < 8; nt++)
#pragma unroll
            for (int i = 0; i < 4; i++) acc[mt][nt][i] = 0.f;

    const int nch = K2tot / TKc2;

    auto load_stage = [&](int c, int s) {
        uint32_t* sa = sm + s * STG_WORDS;
        uint32_t* sb = sa + TM * AST2;
        const __half2* Ab = A + (size_t)m0 * K2tot + c * TKc2;
        const __half2* Bb = B + (size_t)(c * TKc2) * Ntot + n0;
#pragma unroll
        for (int i = 0; i < 4; i++) {
            int idx = tid + i * 128;
            int r = idx >> 2, cc = idx & 3;
            CP_ASYNC16(smem_u32(sa + r * AST2 + cc * 4), Ab + (size_t)r * K2tot + cc * 4);
        }
#pragma unroll
        for (int i = 0; i < 4; i++) {
            int idx = tid + i * 128;
            int r = idx >> 5, n4 = idx & 31;
            CP_ASYNC16(smem_u32(sb + r * BST2 + n4 * 4), Bb + (size_t)r * Ntot + n4 * 4);
        }
        CP_COMMIT();
    };

    load_stage(0, 0);
    load_stage(1, 1);
    load_stage(2, 2);

    for (int c = 0; c < nch; c++) {
        if (c + 3 <= nch)      asm volatile("cp.async.wait_group 2;" ::: "memory");
        else if (c + 2 == nch) asm volatile("cp.async.wait_group 1;" ::: "memory");
        else                   asm volatile("cp.async.wait_group 0;" ::: "memory");
        __syncthreads();
        if (c + 3 < nch) load_stage(c + 3, (c + 3) % NST);

        const uint32_t* sa = sm + (c % NST) * STG_WORDS;
        const uint32_t* sb = sa + TM * AST2;
#pragma unroll
        for (int ks = 0; ks < 2; ks++) {
            uint32_t a[4][4];
#pragma unroll
            for (int mt = 0; mt < 4; mt++) {
                int mm = wm + mt * 16 + l4;
                int base = mm * AST2 + ks * 8 + la3;
                a[mt][0] = sa[base];
                a[mt][1] = sa[base + 8 * AST2];
                a[mt][2] = sa[base + 4];
                a[mt][3] = sa[base + 8 * AST2 + 4];
            }
            uint32_t b[8][2];
#pragma unroll
            for (int nt = 0; nt < 8; nt++) {
                int nn = wn + nt * 8 + l4;
                b[nt][0] = sb[(ks * 8 + la3) * BST2 + nn];
                b[nt][1] = sb[(ks * 8 + la3 + 4) * BST2 + nn];
            }
#pragma unroll
            for (int mt = 0; mt < 4; mt++)
#pragma unroll
                for (int nt = 0; nt < 8; nt++) {
                    asm volatile(
                        "mma.sync.aligned.m16n8k16.row.col.f32.f16.f16.f32 "
                        "{%0,%1,%2,%3}, {%4,%5,%6,%7}, {%8,%9}, {%0,%1,%2,%3};"
                        : "+f"(acc[mt][nt][0]), "+f"(acc[mt][nt][1]),
                          "+f"(acc[mt][nt][2]), "+f"(acc[mt][nt][3])
                        : "r"(a[mt][0]), "r"(a[mt][1]), "r"(a[mt][2]), "r"(a[mt][3]),
                          "r"(b[nt][0]), "r"(b[nt][1]));
                }
        }
    }

#pragma unroll
    for (int mt = 0; mt < 4; mt++) {
#pragma unroll
        for (int nt = 0; nt < 8; nt++) {
            int row = m0 + wm + mt * 16 + l4;
            int col = n0 + wn + nt * 8 + la3 * 2;
            *reinterpret_cast<float2*>(&C[(size_t)row * Ntot + col]) =
                make_float2(acc[mt][nt][0], acc[mt][nt][1]);
            *reinterpret_cast<float2*>(&C[(size_t)(row + 8) * Ntot + col]) =
                make_float2(acc[mt][nt][2], acc[mt][nt][3]);
        }
    }
}

// ---------------- pack Wq|Wk|Wv|Wg -> g_Wch [K/2][6144] half2 -------------------
__global__ void pack_w_kernel(const float* __restrict__ Wq, const float* __restrict__ Wk,
                              const float* __restrict__ Wv, const float* __restrict__ Wg) {
    size_t n = (size_t)(Dm / 2) * NPRE;
    for (size_t i = (size_t)blockIdx.x * blockDim.x + threadIdx.x; i < n;
         i += (size_t)gridDim.x * blockDim.x) {
        int col = (int)(i % NPRE);
        int k2 = (int)(i / NPRE);
        const float* src; int c;
        if (col < 1024)       { src = Wq; c = col;        }
        else if (col < 2048)  { src = Wk; c = col - 1024; }
        else if (col < 4096)  { src = Wv; c = col - 2048; }
        else                  { src = Wg; c = col - 4096; }
        int ncol = (col < 2048) ? 1024 : 2048;
        float v0 = src[(size_t)(2 * k2) * ncol + c];
        float v1 = src[(size_t)(2 * k2 + 1) * ncol + c];
        g_Wch[i] = __floats2half2_rn(v0, v1);
    }
}

__global__ void pack_wo_kernel(const float* __restrict__ Wo) {
    size_t n = (size_t)(Dm / 2) * Dm;
    for (size_t i = (size_t)blockIdx.x * blockDim.x + threadIdx.x; i < n;
         i += (size_t)gridDim.x * blockDim.x) {
        int col = (int)(i % Dm);
        int k2 = (int)(i / Dm);
        float v0 = Wo[(size_t)(2 * k2) * Dm + col];
        float v1 = Wo[(size_t)(2 * k2 + 1) * Dm + col];
        g_Woh[i] = __floats2half2_rn(v0, v1);
    }
}

__global__ void pack_x_kernel(const float* __restrict__ x) {
    size_t n = (size_t)Bsz * Tn * Dm / 2;
    for (size_t i = (size_t)blockIdx.x * blockDim.x + threadIdx.x; i < n;
         i += (size_t)gridDim.x * blockDim.x) {
        float2 v = reinterpret_cast<const float2*>(x)[i];
        g_xh[i] = __floats2half2_rn(v.x, v.y);
    }
}

// ---------------- fused beta/g projection + activations ------------------------
__global__ void betag_fused_kernel(const float* __restrict__ x,
                                   const float* __restrict__ Wb, const float* __restrict__ Wa,
                                   const float* __restrict__ A_log,
                                   const float* __restrict__ dt_bias) {
    int wid = threadIdx.x >> 5, lane = threadIdx.x & 31;
    int row = blockIdx.x * 8 + wid;
    if (row >= Bsz * Tn) return;
    const float* xr = x + (size_t)row * Dm;
    float accB[8], accA[8];
#pragma unroll
    for (int h = 0; h < 8; h++) { accB[h] = 0.f; accA[h] = 0.f; }
    for (int k = lane; k < Dm; k += 32) {
        float xv = xr[k];
        const float4* wb = reinterpret_cast<const float4*>(Wb + (size_t)k * 8);
        const float4* wa = reinterpret_cast<const float4*>(Wa + (size_t)k * 8);
        float4 b0 = wb[0], b1 = wb[1], a0 = wa[0], a1 = wa[1];
        accB[0] += xv * b0.x; accB[1] += xv * b0.y; accB[2] += xv * b0.z; accB[3] += xv * b0.w;
        accB[4] += xv * b1.x; accB[5] += xv * b1.y; accB[6] += xv * b1.z; accB[7] += xv * b1.w;
        accA[0] += xv * a0.x; accA[1] += xv * a0.y; accA[2] += xv * a0.z; accA[3] += xv * a0.w;
        accA[4] += xv * a1.x; accA[5] += xv * a1.y; accA[6] += xv * a1.z; accA[7] += xv * a1.w;
    }
#pragma unroll
    for (int h = 0; h < 8; h++) {
#pragma unroll
        for (int m = 16; m; m >>= 1) {
            accB[h] += __shfl_xor_sync(0xffffffffu, accB[h], m);
            accA[h] += __shfl_xor_sync(0xffffffffu, accA[h], m);
        }
    }
    if (lane < 8) {
        int h = lane;
        float beta = 1.f / (1.f + expf(-accB[h]));
        float xg = accA[h] + dt_bias[h];
        float sp = (xg > 20.f) ? xg : log1pf(expf(xg));
        float gg = -expf(A_log[h]) * sp;
        int b = row / Tn, t = row % Tn;
        size_t o = (size_t)(b * Hh + h) * Tn + t;
        g_eg[o] = expf(gg);
        g_beta[o] = beta;
    }
}

// ---------------- causal dwconv + silu + l2norm for q/k (4 t's per block) ------
__global__ void convnorm_qk4_kernel(const float* __restrict__ convw,
                                    float* __restrict__ out, int off, float scale) {
    int h  = blockIdx.x & 7;
    int tq = (blockIdx.x >> 3) & (Tn / 4 - 1);
    int b  = blockIdx.x >> (3 + 10);
    int t0 = tq * 4;
    int c  = h * DK + threadIdx.x;

    const float* base = g_pre + (size_t)b * Tn * NPRE + off + c;
    float w0 = convw[(size_t)c * Wc + 0];
    float w1 = convw[(size_t)c * Wc + 1];
    float w2 = convw[(size_t)c * Wc + 2];
    float w3 = convw[(size_t)c * Wc + 3];

    float r[7];
#pragma unroll
    for (int i = 0; i < 7; i++) {
        int tt = t0 - 3 + i;
        r[i] = (tt >= 0) ? base[(size_t)tt * NPRE] : 0.f;
    }
    float s[4], ss[4];
#pragma unroll
    for (int j = 0; j < 4; j++) {
        float a = r[j] * w0 + r[j + 1] * w1 + r[j + 2] * w2 + r[j + 3] * w3;
        s[j] = siluf(a);
        ss[j] = s[j] * s[j];
    }
#pragma unroll
    for (int m = 16; m; m >>= 1) {
#pragma unroll
        for (int j = 0; j < 4; j++)
            ss[j] += __shfl_xor_sync(0xffffffffu, ss[j], m);
    }
    __shared__ float wsum[4][4];
    if ((threadIdx.x & 31) == 0) {
        int wd = threadIdx.x >> 5;
#pragma unroll
        for (int j = 0; j < 4; j++) wsum[wd][j] = ss[j];
    }
    __syncthreads();
    size_t ob = ((size_t)(b * Hh + h) * Tn + t0) * DK + threadIdx.x;
#pragma unroll
    for (int j = 0; j < 4; j++) {
        float tot = wsum[0][j] + wsum[1][j] + wsum[2][j] + wsum[3][j];
        out[ob + (size_t)j * DK] = s[j] * rsqrtf(tot + 1e-6f) * scale;
    }
}

// ---------------- causal dwconv + silu for v (4 t's per thread) -----------------
__global__ void convsilu_v4_kernel(const float* __restrict__ convw) {
    size_t total = (size_t)Bsz * (Tn / 4) * VC;
    for (size_t idx = (size_t)blockIdx.x * blockDim.x + threadIdx.x;
         idx < total; idx += (size_t)gridDim.x * blockDim.x) {
        int c  = (int)(idx % VC);
        int tq = (int)((idx / VC) % (Tn / 4));
        int b  = (int)(idx / ((size_t)VC * (Tn / 4)));
        int t0 = tq * 4;
        int h = c >> 8, dv = c & 255;

        const float* base = g_pre + (size_t)b * Tn * NPRE + 2048 + c;
        float w0 = convw[(size_t)c * Wc + 0];
        float w1 = convw[(size_t)c * Wc + 1];
        float w2 = convw[(size_t)c * Wc + 2];
        float w3 = convw[(size_t)c * Wc + 3];

        float r[7];
#pragma unroll
        for (int i = 0; i < 7; i++) {
            int tt = t0 - 3 + i;
            r[i] = (tt >= 0) ? base[(size_t)tt * NPRE] : 0.f;
        }
        size_t ob = ((size_t)(b * Hh + h) * Tn + t0) * DV + dv;
#pragma unroll
        for (int j = 0; j < 4; j++) {
            float a = r[j] * w0 + r[j + 1] * w1 + r[j + 2] * w2 + r[j + 3] * w3;
            g_vc[ob + (size_t)j * DV] = siluf(a);
        }
    }
}

// ---------------- k_{t+1} . k_t dots --------------------------------------------
__global__ void kk_kernel() {
    int wid = threadIdx.x >> 5, lane = threadIdx.x & 31;
    int idx = blockIdx.x * 8 + wid;              // bh*Tn + t
    if (idx >= BH * Tn) return;
    int t = idx & (Tn - 1);
    float s = 0.f;
    if (t + 1 < Tn) {
        const float* k0 = g_kn + (size_t)idx * DK;
        float4 a = reinterpret_cast<const float4*>(k0)[lane];
        float4 b = reinterpret_cast<const float4*>(k0 + DK)[lane];
        s = a.x * b.x + a.y * b.y + a.z * b.z + a.w * b.w;
    }
#pragma unroll
    for (int m = 16; m; m >>= 1) s += __shfl_xor_sync(0xffffffffu, s, m);
    if (lane == 0) g_kk[idx] = s;
}

// ---------------- gated delta-rule recurrence (R12 + SW-pipelined LDS) ----------
// 256 threads: col = tid>>3 (32 value-cols), sub = tid&7 (16 rows each).
// p_{t+1} = eg_t*(k_{t+1}.S_{t-1}) + (k_{t+1}.k_t)*w_t; o deferred/batched.
// kn/qr register double-buffered: loads issued one iteration ahead of use.
#define DVT 32
#define STAGE 32
#define SUBW2 20
#define SKROW 160                  // 8*SUBW2
#define OFF_SK 0
#define OFF_SQ (OFF_SK + (STAGE+1)*SKROW)   // 5280
#define OFF_SV (OFF_SQ + STAGE*SKROW)       // 10400
#define OFF_OP (OFF_SV + STAGE*DVT)         // 11424
#define OFF_EG (OFF_OP + STAGE*256)         // 19616
#define OFF_BT (OFF_EG + STAGE)
#define OFF_CC (OFF_BT + STAGE)
#define DELTA_SMEM ((OFF_CC + STAGE) * 4)   // 78848 bytes

__global__ void __launch_bounds__(256, 1) delta_kernel() {
    extern __shared__ float dsm[];
    float* sK  = dsm + OFF_SK;
    float* sQ  = dsm + OFF_SQ;
    float* sV  = dsm + OFF_SV;
    float* oP  = dsm + OFF_OP;
    float* sEg = dsm + OFF_EG;
    float* sBt = dsm + OFF_BT;
    float* sC  = dsm + OFF_CC;

    int bh = blockIdx.x;
    int vt = blockIdx.y;
    int tid = threadIdx.x;           // 256
    int col = tid >> 3;              // 0..31
    int sub = tid & 7;               // rows [sub*16, sub*16+16)

    const float* kb  = g_kn   + (size_t)bh * Tn * DK;
    const float* qb  = g_qn   + (size_t)bh * Tn * DK;
    const float* vb  = g_vc   + (size_t)bh * Tn * DV;
    const float* egb = g_eg   + (size_t)bh * Tn;
    const float* btb = g_beta + (size_t)bh * Tn;
    const float* ccb = g_kk   + (size_t)bh * Tn;
    float* ob        = g_o    + (size_t)bh * Tn * DV;

    float S[16];
#pragma unroll
    for (int i = 0; i < 16; i++) S[i] = 0.f;
    float E_prev = 0.f, w_prev = 0.f, c_prev = 0.f, eg_prev = 0.f;

    for (int c0 = 0; c0 < Tn; c0 += STAGE) {
        __syncthreads();
#pragma unroll
        for (int l = 0; l < 4; l++) {
            int linear = tid + l * 256;
            int tl = linear >> 5;
            int v4 = linear & 31;
            float4 kv = reinterpret_cast<const float4*>(kb + (size_t)(c0 + tl) * DK)[v4];
            float4 qv = reinterpret_cast<const float4*>(qb + (size_t)(c0 + tl) * DK)[v4];
            int off = (v4 >> 2) * SUBW2 + (v4 & 3) * 4;
            *reinterpret_cast<float4*>(&sK[tl * SKROW + off]) = kv;
            *reinterpret_cast<float4*>(&sQ[tl * SKROW + off]) = qv;
        }
        if (tid < 32) {
            int row = c0 + 32; if (row > Tn - 1) row = Tn - 1;
            float4 kv = reinterpret_cast<const float4*>(kb + (size_t)row * DK)[tid];
            int off = (tid >> 2) * SUBW2 + (tid & 3) * 4;
            *reinterpret_cast<float4*>(&sK[32 * SKROW + off]) = kv;
        }
        {
            int tl = tid >> 3;
            int v4 = tid & 7;
            float4 vv = reinterpret_cast<const float4*>(vb + (size_t)(c0 + tl) * DV + vt * DVT)[v4];
            *reinterpret_cast<float4*>(&sV[tl * DVT + v4 * 4]) = vv;
        }
        if (tid < STAGE) {
            sEg[tid] = egb[c0 + tid];
            sBt[tid] = btb[c0 + tid];
            sC[tid]  = ccb[c0 + tid];
        }
        __syncthreads();

        // register pipeline: kq = k_s, knb = k_{s+1}, qrb = q_s
        float4 kq[4], knb[4], qrb[4];
        {
            const float4* kr0 = reinterpret_cast<const float4*>(&sK[sub * SUBW2]);
            const float4* kr1 = reinterpret_cast<const float4*>(&sK[SKROW + sub * SUBW2]);
            const float4* qr0 = reinterpret_cast<const float4*>(&sQ[sub * SUBW2]);
#pragma unroll
            for (int j = 0; j < 4; j++) { kq[j] = kr0[j]; knb[j] = kr1[j]; qrb[j] = qr0[j]; }
        }

#pragma unroll 4
        for (int s = 0; s < STAGE; s++) {
            float eg = sEg[s], bt = sBt[s], cc = sC[s];
            float v = sV[s * DVT + col];

            // prefetch next iteration's k_{s+2} and q_{s+1} (clamped; unused values at edge)
            int kpf = (s + 2 <= STAGE) ? (s + 2) : STAGE;
            int qpf = (s + 1 < STAGE) ? (s + 1) : (STAGE - 1);
            const float4* krn = reinterpret_cast<const float4*>(&sK[kpf * SKROW + sub * SUBW2]);
            const float4* qrn = reinterpret_cast<const float4*>(&sQ[qpf * SKROW + sub * SUBW2]);
            float4 kn_next[4], q_next[4];
#pragma unroll
            for (int j = 0; j < 4; j++) { kn_next[j] = krn[j]; q_next[j] = qrn[j]; }

            // scalar recurrence: p_t = eg_{t-1}*E_{t-1} + c_{t-1}*w_{t-1}
            float p = eg_prev * E_prev + c_prev * w_prev;
            float w = bt * (v - eg * p);

            // E_t = k_{t+1} . S_{t-1} (pre-update) using buffered knb
            float e0 = 0.f, e1 = 0.f, e2 = 0.f, e3 = 0.f;
#pragma unroll
            for (int j = 0; j < 4; j++) {
                e0 += knb[j].x * S[4 * j + 0];
                e1 += knb[j].y * S[4 * j + 1];
                e2 += knb[j].z * S[4 * j + 2];
                e3 += knb[j].w * S[4 * j + 3];
            }
            float E = (e0 + e1) + (e2 + e3);
            E += __shfl_xor_sync(0xffffffffu, E, 1);
            E += __shfl_xor_sync(0xffffffffu, E, 2);
            E += __shfl_xor_sync(0xffffffffu, E, 4);

            // S = eg*S + k*w ; o partial = q . S_new (deferred reduction)
            float o0 = 0.f, o1 = 0.f, o2 = 0.f, o3 = 0.f;
#pragma unroll
            for (int j = 0; j < 4; j++) {
                float4 qv = qrb[j];
                S[4 * j + 0] = eg * S[4 * j + 0] + kq[j].x * w;
                S[4 * j + 1] = eg * S[4 * j + 1] + kq[j].y * w;
                S[4 * j + 2] = eg * S[4 * j + 2] + kq[j].z * w;
                S[4 * j + 3] = eg * S[4 * j + 3] + kq[j].w * w;
                o0 += qv.x * S[4 * j + 0];
                o1 += qv.y * S[4 * j + 1];
                o2 += qv.z * S[4 * j + 2];
                o3 += qv.w * S[4 * j + 3];
            }
            oP[s * 256 + col * 8 + sub] = (o0 + o1) + (o2 + o3);

            E_prev = E; w_prev = w; c_prev = cc; eg_prev = eg;
#pragma unroll
            for (int j = 0; j < 4; j++) { kq[j] = knb[j]; knb[j] = kn_next[j]; qrb[j] = q_next[j]; }
        }
        __syncthreads();

#pragma unroll
        for (int r = 0; r < 4; r++) {
            int idx = r * 256 + tid;
            int t = idx >> 5, cl = idx & 31;
            const float* b = &oP[t * 256 + cl * 8];
            float sum = ((b[0] + b[1]) + (b[2] + b[3])) + ((b[4] + b[5]) + (b[6] + b[7]));
            ob[(size_t)(c0 + t) * DV + vt * DVT + cl] = sum;
        }
    }
}

// ---------------- gated RMSNorm + silu(gate), half2 output ---------------------
__global__ void gatednorm_kernel(const float* __restrict__ g_norm_w) {
    int idx = blockIdx.x;
    int h = idx % Hh;
    int t = (idx / Hh) % Tn;
    int b = idx / (Hh * Tn);
    int dv = threadIdx.x * 2;
    size_t obase = ((size_t)(b * Hh + h) * Tn + t) * DV;
    float o0 = g_o[obase + dv];
    float o1 = g_o[obase + dv + 1];
    float ss = o0 * o0 + o1 * o1;
#pragma unroll
    for (int m = 16; m; m >>= 1) ss += __shfl_xor_sync(0xffffffffu, ss, m);
    __shared__ float wsum[4];
    if ((threadIdx.x & 31) == 0) wsum[threadIdx.x >> 5] = ss;
    __syncthreads();
    float tot = wsum[0] + wsum[1] + wsum[2] + wsum[3];
    float r = rsqrtf(tot * (1.f / DV) + 1e-5f);
    size_t gb = ((size_t)(b * Tn + t)) * NPRE + 4096 + h * DV + dv;
    float gt0 = g_pre[gb], gt1 = g_pre[gb + 1];
    float v0 = o0 * r * g_norm_w[dv] * siluf(gt0);
    float v1 = o1 * r * g_norm_w[dv + 1] * siluf(gt1);
    g_onh[((size_t)(b * Tn + t)) * (VC / 2) + (h * DV + dv) / 2] = __floats2half2_rn(v0, v1);
}

// ---------------- launch --------------------------------------------------------
extern "C" void kernel_launch(void* const* d_in, const int* in_sizes, int n_in,
                              void* d_out, int out_size) {
    const float* x       = (const float*)d_in[0];
    const float* Wq      = (const float*)d_in[1];
    const float* Wk      = (const float*)d_in[2];
    const float* Wv      = (const float*)d_in[3];
    const float* Wb      = (const float*)d_in[4];
    const float* Wa      = (const float*)d_in[5];
    const float* Wg      = (const float*)d_in[6];
    const float* Wo      = (const float*)d_in[7];
    const float* conv_q  = (const float*)d_in[8];
    const float* conv_k  = (const float*)d_in[9];
    const float* conv_v  = (const float*)d_in[10];
    const float* A_log   = (const float*)d_in[11];
    const float* dt_bias = (const float*)d_in[12];
    const float* gnw     = (const float*)d_in[13];
    float* out = (float*)d_out;

    float *pre, *qn, *kn;
    __half2 *Wch, *Woh, *xh, *onh;
    cudaGetSymbolAddress((void**)&pre, g_pre);
    cudaGetSymbolAddress((void**)&Wch, g_Wch);
    cudaGetSymbolAddress((void**)&Woh, g_Woh);
    cudaGetSymbolAddress((void**)&xh,  g_xh);
    cudaGetSymbolAddress((void**)&onh, g_onh);
    cudaGetSymbolAddress((void**)&qn,  g_qn);
    cudaGetSymbolAddress((void**)&kn,  g_kn);

    cudaFuncSetAttribute(gemm_h, cudaFuncAttributeMaxDynamicSharedMemorySize, SMEM_GEMMH);
    cudaFuncSetAttribute(delta_kernel, cudaFuncAttributeMaxDynamicSharedMemorySize, DELTA_SMEM);

    const int M = Bsz * Tn;   // 8192

    pack_w_kernel<<<1024, 256>>>(Wq, Wk, Wv, Wg);
    pack_wo_kernel<<<512, 256>>>(Wo);
    pack_x_kernel<<<1024, 256>>>(x);

    // big projection GEMM: pre[8192,6144] = xh @ Wch
    gemm_h<<<dim3(NPRE / TN, M / TM), 128, SMEM_GEMMH>>>(xh, Wch, pre, M, NPRE, Dm / 2);

    betag_fused_kernel<<<M / 8, 256>>>(x, Wb, Wa, A_log, dt_bias);

    convnorm_qk4_kernel<<<Bsz * (Tn / 4) * Hh, DK>>>(conv_q, qn, 0, 0.08838834764831845f);
    convnorm_qk4_kernel<<<Bsz * (Tn / 4) * Hh, DK>>>(conv_k, kn, 1024, 1.0f);
    convsilu_v4_kernel<<<4096, 256>>>(conv_v);

    kk_kernel<<<BH * Tn / 8, 256>>>();

    {
        dim3 grid(BH, DV / DVT);
        delta_kernel<<<grid, 256, DELTA_SMEM>>>();
    }

    gatednorm_kernel<<<Bsz * Tn * Hh, DV / 2>>>(gnw);

    // output GEMM: out[8192,2048] = onh @ Woh
    gemm_h<<<dim3(Dm / TN, M / TM), 128, SMEM_GEMMH>>>(onh, Woh, out, M, Dm, Dm / 2);
}

// round 15
// speedup vs baseline: 1.1140x; 1.0181x over previous
#include <cuda_runtime.h>
#include <cuda_fp16.h>
#include <math.h>
#include <stdint.h>

// Problem constants
#define Bsz 2
#define Tn 4096
#define Dm 2048
#define Hh 8
#define DK 128
#define DV 256
#define Wc 4
#define BH (Bsz*Hh)          // 16
#define QKC (Hh*DK)          // 1024
#define VC  (Hh*DV)          // 2048
#define NPRE 6144            // packed q|k|v|g columns

// ---------------- scratch (device globals; no allocations allowed) -------------
__device__ float   g_pre [(size_t)Bsz*Tn*NPRE];   // packed projections (fp32)
__device__ __half2 g_Wch [(size_t)(Dm/2)*NPRE];   // packed weights, half2 pairs along K
__device__ __half2 g_Woh [(size_t)(Dm/2)*Dm];     // Wo, half2 pairs along K
__device__ __half2 g_xh  [(size_t)Bsz*Tn*(Dm/2)]; // x, half2 pairs along K
__device__ __half2 g_onh [(size_t)Bsz*Tn*(VC/2)]; // gated-norm output, half2 pairs
__device__ float   g_qn  [(size_t)BH*Tn*DK];
__device__ float   g_kn  [(size_t)BH*Tn*DK];
__device__ float   g_vc  [(size_t)BH*Tn*DV];
__device__ float   g_eg  [(size_t)BH*Tn];
__device__ float   g_beta[(size_t)BH*Tn];
__device__ float   g_kk  [(size_t)BH*Tn];         // c_t = k_{t+1} . k_t
__device__ float   g_o   [(size_t)BH*Tn*DV];

__device__ __forceinline__ float siluf(float x) { return x / (1.f + __expf(-x)); }

__device__ __forceinline__ uint32_t smem_u32(const void* p) {
    uint32_t a;
    asm("{ .reg .u64 t; cvta.to.shared.u64 t, %1; cvt.u32.u64 %0, t; }" : "=r"(a) : "l"(p));
    return a;
}

#define CP_ASYNC16(dst, src) \
    asm volatile("cp.async.cg.shared.global [%0], [%1], 16;" \
        :: "r"((uint32_t)(dst)), "l"(src) : "memory")
#define CP_COMMIT() asm volatile("cp.async.commit_group;" ::: "memory")

// ============ fp16 m16n8k16 GEMM, fp32 accum, 4-stage cp.async pipeline ========
#define TM 128
#define TN 128
#define TKc2 16
#define AST2 20
#define BST2 136
#define STG_WORDS (TM*AST2 + TKc2*BST2)    // 4736
#define NST 4
#define SMEM_GEMMH (NST*STG_WORDS*4)       // 75776 bytes

__global__ void __launch_bounds__(128, 2) gemm_h(
    const __half2* __restrict__ A, const __half2* __restrict__ B,
    float* __restrict__ C, int Mtot, int Ntot, int K2tot) {
    extern __shared__ uint32_t sm[];
    const int tid = threadIdx.x, lane = tid & 31, wid = tid >> 5;
    const int wm = (wid & 1) * 64;
    const int wn = (wid >> 1) * 64;
    const int m0 = blockIdx.y * TM, n0 = blockIdx.x * TN;
    const int la3 = lane & 3, l4 = lane >> 2;

    float acc[4][8][4];
#pragma unroll
    for (int mt = 0; mt < 4; mt++)
#pragma unroll
        for (int nt = 0; nt < 8; nt++)
#pragma unroll
            for (int i = 0; i < 4; i++) acc[mt][nt][i] = 0.f;

    const int nch = K2tot / TKc2;

    auto load_stage = [&](int c, int s) {
        uint32_t* sa = sm + s * STG_WORDS;
        uint32_t* sb = sa + TM * AST2;
        const __half2* Ab = A + (size_t)m0 * K2tot + c * TKc2;
        const __half2* Bb = B + (size_t)(c * TKc2) * Ntot + n0;
#pragma unroll
        for (int i = 0; i < 4; i++) {
            int idx = tid + i * 128;
            int r = idx >> 2, cc = idx & 3;
            CP_ASYNC16(smem_u32(sa + r * AST2 + cc * 4), Ab + (size_t)r * K2tot + cc * 4);
        }
#pragma unroll
        for (int i = 0; i < 4; i++) {
            int idx = tid + i * 128;
            int r = idx >> 5, n4 = idx & 31;
            CP_ASYNC16(smem_u32(sb + r * BST2 + n4 * 4), Bb + (size_t)r * Ntot + n4 * 4);
        }
        CP_COMMIT();
    };

    load_stage(0, 0);
    load_stage(1, 1);
    load_stage(2, 2);

    for (int c = 0; c < nch; c++) {
        if (c + 3 <= nch)      asm volatile("cp.async.wait_group 2;" ::: "memory");
        else if (c + 2 == nch) asm volatile("cp.async.wait_group 1;" ::: "memory");
        else                   asm volatile("cp.async.wait_group 0;" ::: "memory");
        __syncthreads();
        if (c + 3 < nch) load_stage(c + 3, (c + 3) % NST);

        const uint32_t* sa = sm + (c % NST) * STG_WORDS;
        const uint32_t* sb = sa + TM * AST2;
#pragma unroll
        for (int ks = 0; ks < 2; ks++) {
            uint32_t a[4][4];
#pragma unroll
            for (int mt = 0; mt < 4; mt++) {
                int mm = wm + mt * 16 + l4;
                int base = mm * AST2 + ks * 8 + la3;
                a[mt][0] = sa[base];
                a[mt][1] = sa[base + 8 * AST2];
                a[mt][2] = sa[base + 4];
                a[mt][3] = sa[base + 8 * AST2 + 4];
            }
            uint32_t b[8][2];
#pragma unroll
            for (int nt = 0; nt < 8; nt++) {
                int nn = wn + nt * 8 + l4;
                b[nt][0] = sb[(ks * 8 + la3) * BST2 + nn];
                b[nt][1] = sb[(ks * 8 + la3 + 4) * BST2 + nn];
            }
#pragma unroll
            for (int mt = 0; mt < 4; mt++)
#pragma unroll
                for (int nt = 0; nt < 8; nt++) {
                    asm volatile(
                        "mma.sync.aligned.m16n8k16.row.col.f32.f16.f16.f32 "
                        "{%0,%1,%2,%3}, {%4,%5,%6,%7}, {%8,%9}, {%0,%1,%2,%3};"
                        : "+f"(acc[mt][nt][0]), "+f"(acc[mt][nt][1]),
                          "+f"(acc[mt][nt][2]), "+f"(acc[mt][nt][3])
                        : "r"(a[mt][0]), "r"(a[mt][1]), "r"(a[mt][2]), "r"(a[mt][3]),
                          "r"(b[nt][0]), "r"(b[nt][1]));
                }
        }
    }

#pragma unroll
    for (int mt = 0; mt < 4; mt++) {
#pragma unroll
        for (int nt = 0; nt < 8; nt++) {
            int row = m0 + wm + mt * 16 + l4;
            int col = n0 + wn + nt * 8 + la3 * 2;
            *reinterpret_cast<float2*>(&C[(size_t)row * Ntot + col]) =
                make_float2(acc[mt][nt][0], acc[mt][nt][1]);
            *reinterpret_cast<float2*>(&C[(size_t)(row + 8) * Ntot + col]) =
                make_float2(acc[mt][nt][2], acc[mt][nt][3]);
        }
    }
}

// ---------------- pack Wq|Wk|Wv|Wg -> g_Wch [K/2][6144] half2 -------------------
__global__ void pack_w_kernel(const float* __restrict__ Wq, const float* __restrict__ Wk,
                              const float* __restrict__ Wv, const float* __restrict__ Wg) {
    size_t n = (size_t)(Dm / 2) * NPRE;
    for (size_t i = (size_t)blockIdx.x * blockDim.x + threadIdx.x; i < n;
         i += (size_t)gridDim.x * blockDim.x) {
        int col = (int)(i % NPRE);
        int k2 = (int)(i / NPRE);
        const float* src; int c;
        if (col < 1024)       { src = Wq; c = col;        }
        else if (col < 2048)  { src = Wk; c = col - 1024; }
        else if (col < 4096)  { src = Wv; c = col - 2048; }
        else                  { src = Wg; c = col - 4096; }
        int ncol = (col < 2048) ? 1024 : 2048;
        float v0 = src[(size_t)(2 * k2) * ncol + c];
        float v1 = src[(size_t)(2 * k2 + 1) * ncol + c];
        g_Wch[i] = __floats2half2_rn(v0, v1);
    }
}

__global__ void pack_wo_kernel(const float* __restrict__ Wo) {
    size_t n = (size_t)(Dm / 2) * Dm;
    for (size_t i = (size_t)blockIdx.x * blockDim.x + threadIdx.x; i < n;
         i += (size_t)gridDim.x * blockDim.x) {
        int col = (int)(i % Dm);
        int k2 = (int)(i / Dm);
        float v0 = Wo[(size_t)(2 * k2) * Dm + col];
        float v1 = Wo[(size_t)(2 * k2 + 1) * Dm + col];
        g_Woh[i] = __floats2half2_rn(v0, v1);
    }
}

__global__ void pack_x_kernel(const float* __restrict__ x) {
    size_t n = (size_t)Bsz * Tn * Dm / 2;
    for (size_t i = (size_t)blockIdx.x * blockDim.x + threadIdx.x; i < n;
         i += (size_t)gridDim.x * blockDim.x) {
        float2 v = reinterpret_cast<const float2*>(x)[i];
        g_xh[i] = __floats2half2_rn(v.x, v.y);
    }
}

// ---------------- blocked fp32 beta/g projection + activations -----------------
// 128 blocks x 256 threads; block handles 64 rows, k-tiles of 128.
// Thread owns one row (r = tid>>2) and 4 of 16 outputs (jq = tid&3).
// jq 0,1 -> Wb outputs (beta, h = jq*4+i); jq 2,3 -> Wa outputs (g, h = (jq-2)*4+i).
#define BGR 64
#define BGK 128
#define BXST 132
__global__ void __launch_bounds__(256) betag_gemm_kernel(
    const float* __restrict__ x,
    const float* __restrict__ Wb, const float* __restrict__ Wa,
    const float* __restrict__ A_log, const float* __restrict__ dt_bias) {
    __shared__ float sX[BGR * BXST];
    __shared__ float sW[BGK * 16];

    int tid = threadIdx.x;
    int row0 = blockIdx.x * BGR;
    int r = tid >> 2;          // local row 0..63
    int jq = tid & 3;          // output quad

    float acc[4] = {0.f, 0.f, 0.f, 0.f};

    for (int kt = 0; kt < Dm; kt += BGK) {
        __syncthreads();
        // x tile: 64 rows x 128 k = 2048 float4 (256 thr x 8)
#pragma unroll
        for (int i = 0; i < 8; i++) {
            int linear = tid + i * 256;
            int rr = linear >> 5, cc = linear & 31;
            float4 v = *reinterpret_cast<const float4*>(
                x + (size_t)(row0 + rr) * Dm + kt + cc * 4);
            *reinterpret_cast<float4*>(&sX[rr * BXST + cc * 4]) = v;
        }
        // W tile: 128 k x 16 (Wb cols 0..7, Wa cols 8..15) = 512 float4 (256 thr x 2)
#pragma unroll
        for (int i = 0; i < 2; i++) {
            int linear = tid + i * 256;
            int kk = linear >> 2, c4 = linear & 3;
            float4 wv;
            if (c4 < 2)
                wv = *reinterpret_cast<const float4*>(Wb + (size_t)(kt + kk) * 8 + c4 * 4);
            else
                wv = *reinterpret_cast<const float4*>(Wa + (size_t)(kt + kk) * 8 + (c4 - 2) * 4);
            *reinterpret_cast<float4*>(&sW[kk * 16 + c4 * 4]) = wv;
        }
        __syncthreads();

#pragma unroll 8
        for (int k = 0; k < BGK; k++) {
            float xv = sX[r * BXST + k];
            float4 wv = *reinterpret_cast<const float4*>(&sW[k * 16 + jq * 4]);
            acc[0] += xv * wv.x;
            acc[1] += xv * wv.y;
            acc[2] += xv * wv.z;
            acc[3] += xv * wv.w;
        }
    }

    int row = row0 + r;
    int b = row / Tn, t = row % Tn;
    if (jq < 2) {
#pragma unroll
        for (int i = 0; i < 4; i++) {
            int h = jq * 4 + i;
            g_beta[(size_t)(b * Hh + h) * Tn + t] = 1.f / (1.f + expf(-acc[i]));
        }
    } else {
#pragma unroll
        for (int i = 0; i < 4; i++) {
            int h = (jq - 2) * 4 + i;
            float xg = acc[i] + dt_bias[h];
            float sp = (xg > 20.f) ? xg : log1pf(expf(xg));
            float gg = -expf(A_log[h]) * sp;
            g_eg[(size_t)(b * Hh + h) * Tn + t] = expf(gg);
        }
    }
}

// ---------------- causal dwconv + silu + l2norm for q/k (4 t's per block) ------
__global__ void convnorm_qk4_kernel(const float* __restrict__ convw,
                                    float* __restrict__ out, int off, float scale) {
    int h  = blockIdx.x & 7;
    int tq = (blockIdx.x >> 3) & (Tn / 4 - 1);
    int b  = blockIdx.x >> (3 + 10);
    int t0 = tq * 4;
    int c  = h * DK + threadIdx.x;

    const float* base = g_pre + (size_t)b * Tn * NPRE + off + c;
    float w0 = convw[(size_t)c * Wc + 0];
    float w1 = convw[(size_t)c * Wc + 1];
    float w2 = convw[(size_t)c * Wc + 2];
    float w3 = convw[(size_t)c * Wc + 3];

    float r[7];
#pragma unroll
    for (int i = 0; i < 7; i++) {
        int tt = t0 - 3 + i;
        r[i] = (tt >= 0) ? base[(size_t)tt * NPRE] : 0.f;
    }
    float s[4], ss[4];
#pragma unroll
    for (int j = 0; j < 4; j++) {
        float a = r[j] * w0 + r[j + 1] * w1 + r[j + 2] * w2 + r[j + 3] * w3;
        s[j] = siluf(a);
        ss[j] = s[j] * s[j];
    }
#pragma unroll
    for (int m = 16; m; m >>= 1) {
#pragma unroll
        for (int j = 0; j < 4; j++)
            ss[j] += __shfl_xor_sync(0xffffffffu, ss[j], m);
    }
    __shared__ float wsum[4][4];
    if ((threadIdx.x & 31) == 0) {
        int wd = threadIdx.x >> 5;
#pragma unroll
        for (int j = 0; j < 4; j++) wsum[wd][j] = ss[j];
    }
    __syncthreads();
    size_t ob = ((size_t)(b * Hh + h) * Tn + t0) * DK + threadIdx.x;
#pragma unroll
    for (int j = 0; j < 4; j++) {
        float tot = wsum[0][j] + wsum[1][j] + wsum[2][j] + wsum[3][j];
        out[ob + (size_t)j * DK] = s[j] * rsqrtf(tot + 1e-6f) * scale;
    }
}

// ---------------- causal dwconv + silu for v (4 t's per thread) -----------------
__global__ void convsilu_v4_kernel(const float* __restrict__ convw) {
    size_t total = (size_t)Bsz * (Tn / 4) * VC;
    for (size_t idx = (size_t)blockIdx.x * blockDim.x + threadIdx.x;
         idx < total; idx += (size_t)gridDim.x * blockDim.x) {
        int c  = (int)(idx % VC);
        int tq = (int)((idx / VC) % (Tn / 4));
        int b  = (int)(idx / ((size_t)VC * (Tn / 4)));
        int t0 = tq * 4;
        int h = c >> 8, dv = c & 255;

        const float* base = g_pre + (size_t)b * Tn * NPRE + 2048 + c;
        float w0 = convw[(size_t)c * Wc + 0];
        float w1 = convw[(size_t)c * Wc + 1];
        float w2 = convw[(size_t)c * Wc + 2];
        float w3 = convw[(size_t)c * Wc + 3];

        float r[7];
#pragma unroll
        for (int i = 0; i < 7; i++) {
            int tt = t0 - 3 + i;
            r[i] = (tt >= 0) ? base[(size_t)tt * NPRE] : 0.f;
        }
        size_t ob = ((size_t)(b * Hh + h) * Tn + t0) * DV + dv;
#pragma unroll
        for (int j = 0; j < 4; j++) {
            float a = r[j] * w0 + r[j + 1] * w1 + r[j + 2] * w2 + r[j + 3] * w3;
            g_vc[ob + (size_t)j * DV] = siluf(a);
        }
    }
}

// ---------------- k_{t+1} . k_t dots --------------------------------------------
__global__ void kk_kernel() {
    int wid = threadIdx.x >> 5, lane = threadIdx.x & 31;
    int idx = blockIdx.x * 8 + wid;              // bh*Tn + t
    if (idx >= BH * Tn) return;
    int t = idx & (Tn - 1);
    float s = 0.f;
    if (t + 1 < Tn) {
        const float* k0 = g_kn + (size_t)idx * DK;
        float4 a = reinterpret_cast<const float4*>(k0)[lane];
        float4 b = reinterpret_cast<const float4*>(k0 + DK)[lane];
        s = a.x * b.x + a.y * b.y + a.z * b.z + a.w * b.w;
    }
#pragma unroll
    for (int m = 16; m; m >>= 1) s += __shfl_xor_sync(0xffffffffu, s, m);
    if (lane == 0) g_kk[idx] = s;
}

// ---------------- gated delta-rule recurrence (R12 version) ---------------------
// 256 threads: col = tid>>3 (32 value-cols), sub = tid&7 (16 rows each).
// p_{t+1} = eg_t*(k_{t+1}.S_{t-1}) + (k_{t+1}.k_t)*w_t; o deferred/batched.
#define DVT 32
#define STAGE 32
#define SUBW2 20
#define SKROW 160                  // 8*SUBW2
#define OFF_SK 0
#define OFF_SQ (OFF_SK + (STAGE+1)*SKROW)   // 5280
#define OFF_SV (OFF_SQ + STAGE*SKROW)       // 10400
#define OFF_OP (OFF_SV + STAGE*DVT)         // 11424
#define OFF_EG (OFF_OP + STAGE*256)         // 19616
#define OFF_BT (OFF_EG + STAGE)
#define OFF_CC (OFF_BT + STAGE)
#define DELTA_SMEM ((OFF_CC + STAGE) * 4)   // 78848 bytes

__global__ void __launch_bounds__(256, 1) delta_kernel() {
    extern __shared__ float dsm[];
    float* sK  = dsm + OFF_SK;
    float* sQ  = dsm + OFF_SQ;
    float* sV  = dsm + OFF_SV;
    float* oP  = dsm + OFF_OP;
    float* sEg = dsm + OFF_EG;
    float* sBt = dsm + OFF_BT;
    float* sC  = dsm + OFF_CC;

    int bh = blockIdx.x;
    int vt = blockIdx.y;
    int tid = threadIdx.x;           // 256
    int col = tid >> 3;              // 0..31
    int sub = tid & 7;               // rows [sub*16, sub*16+16)

    const float* kb  = g_kn   + (size_t)bh * Tn * DK;
    const float* qb  = g_qn   + (size_t)bh * Tn * DK;
    const float* vb  = g_vc   + (size_t)bh * Tn * DV;
    const float* egb = g_eg   + (size_t)bh * Tn;
    const float* btb = g_beta + (size_t)bh * Tn;
    const float* ccb = g_kk   + (size_t)bh * Tn;
    float* ob        = g_o    + (size_t)bh * Tn * DV;

    float S[16];
#pragma unroll
    for (int i = 0; i < 16; i++) S[i] = 0.f;
    float E_prev = 0.f, w_prev = 0.f, c_prev = 0.f, eg_prev = 0.f;

    for (int c0 = 0; c0 < Tn; c0 += STAGE) {
        __syncthreads();
#pragma unroll
        for (int l = 0; l < 4; l++) {
            int linear = tid + l * 256;
            int tl = linear >> 5;
            int v4 = linear & 31;
            float4 kv = reinterpret_cast<const float4*>(kb + (size_t)(c0 + tl) * DK)[v4];
            float4 qv = reinterpret_cast<const float4*>(qb + (size_t)(c0 + tl) * DK)[v4];
            int off = (v4 >> 2) * SUBW2 + (v4 & 3) * 4;
            *reinterpret_cast<float4*>(&sK[tl * SKROW + off]) = kv;
            *reinterpret_cast<float4*>(&sQ[tl * SKROW + off]) = qv;
        }
        if (tid < 32) {
            int row = c0 + 32; if (row > Tn - 1) row = Tn - 1;
            float4 kv = reinterpret_cast<const float4*>(kb + (size_t)row * DK)[tid];
            int off = (tid >> 2) * SUBW2 + (tid & 3) * 4;
            *reinterpret_cast<float4*>(&sK[32 * SKROW + off]) = kv;
        }
        {
            int tl = tid >> 3;
            int v4 = tid & 7;
            float4 vv = reinterpret_cast<const float4*>(vb + (size_t)(c0 + tl) * DV + vt * DVT)[v4];
            *reinterpret_cast<float4*>(&sV[tl * DVT + v4 * 4]) = vv;
        }
        if (tid < STAGE) {
            sEg[tid] = egb[c0 + tid];
            sBt[tid] = btb[c0 + tid];
            sC[tid]  = ccb[c0 + tid];
        }
        __syncthreads();

        float4 kq[4];
        {
            const float4* kr = reinterpret_cast<const float4*>(&sK[sub * SUBW2]);
#pragma unroll
            for (int j = 0; j < 4; j++) kq[j] = kr[j];
        }

#pragma unroll 4
        for (int s = 0; s < STAGE; s++) {
            float eg = sEg[s], bt = sBt[s], cc = sC[s];
            float v = sV[s * DVT + col];

            float p = eg_prev * E_prev + c_prev * w_prev;
            float w = bt * (v - eg * p);

            float4 kn[4];
            const float4* krn = reinterpret_cast<const float4*>(&sK[(s + 1) * SKROW + sub * SUBW2]);
#pragma unroll
            for (int j = 0; j < 4; j++) kn[j] = krn[j];

            float e0 = 0.f, e1 = 0.f, e2 = 0.f, e3 = 0.f;
#pragma unroll
            for (int j = 0; j < 4; j++) {
                e0 += kn[j].x * S[4 * j + 0];
                e1 += kn[j].y * S[4 * j + 1];
                e2 += kn[j].z * S[4 * j + 2];
                e3 += kn[j].w * S[4 * j + 3];
            }
            float E = (e0 + e1) + (e2 + e3);
            E += __shfl_xor_sync(0xffffffffu, E, 1);
            E += __shfl_xor_sync(0xffffffffu, E, 2);
            E += __shfl_xor_sync(0xffffffffu, E, 4);

            const float4* qr = reinterpret_cast<const float4*>(&sQ[s * SKROW + sub * SUBW2]);
            float o0 = 0.f, o1 = 0.f, o2 = 0.f, o3 = 0.f;
#pragma unroll
            for (int j = 0; j < 4; j++) {
                float4 qv = qr[j];
                S[4 * j + 0] = eg * S[4 * j + 0] + kq[j].x * w;
                S[4 * j + 1] = eg * S[4 * j + 1] + kq[j].y * w;
                S[4 * j + 2] = eg * S[4 * j + 2] + kq[j].z * w;
                S[4 * j + 3] = eg * S[4 * j + 3] + kq[j].w * w;
                o0 += qv.x * S[4 * j + 0];
                o1 += qv.y * S[4 * j + 1];
                o2 += qv.z * S[4 * j + 2];
                o3 += qv.w * S[4 * j + 3];
            }
            oP[s * 256 + col * 8 + sub] = (o0 + o1) + (o2 + o3);

            E_prev = E; w_prev = w; c_prev = cc; eg_prev = eg;
#pragma unroll
            for (int j = 0; j < 4; j++) kq[j] = kn[j];
        }
        __syncthreads();

#pragma unroll
        for (int r = 0; r < 4; r++) {
            int idx = r * 256 + tid;
            int t = idx >> 5, cl = idx & 31;
            const float* b = &oP[t * 256 + cl * 8];
            float sum = ((b[0] + b[1]) + (b[2] + b[3])) + ((b[4] + b[5]) + (b[6] + b[7]));
            ob[(size_t)(c0 + t) * DV + vt * DVT + cl] = sum;
        }
    }
}

// ---------------- gated RMSNorm + silu(gate), half2 output ---------------------
__global__ void gatednorm_kernel(const float* __restrict__ g_norm_w) {
    int idx = blockIdx.x;
    int h = idx % Hh;
    int t = (idx / Hh) % Tn;
    int b = idx / (Hh * Tn);
    int dv = threadIdx.x * 2;
    size_t obase = ((size_t)(b * Hh + h) * Tn + t) * DV;
    float o0 = g_o[obase + dv];
    float o1 = g_o[obase + dv + 1];
    float ss = o0 * o0 + o1 * o1;
#pragma unroll
    for (int m = 16; m; m >>= 1) ss += __shfl_xor_sync(0xffffffffu, ss, m);
    __shared__ float wsum[4];
    if ((threadIdx.x & 31) == 0) wsum[threadIdx.x >> 5] = ss;
    __syncthreads();
    float tot = wsum[0] + wsum[1] + wsum[2] + wsum[3];
    float r = rsqrtf(tot * (1.f / DV) + 1e-5f);
    size_t gb = ((size_t)(b * Tn + t)) * NPRE + 4096 + h * DV + dv;
    float gt0 = g_pre[gb], gt1 = g_pre[gb + 1];
    float v0 = o0 * r * g_norm_w[dv] * siluf(gt0);
    float v1 = o1 * r * g_norm_w[dv + 1] * siluf(gt1);
    g_onh[((size_t)(b * Tn + t)) * (VC / 2) + (h * DV + dv) / 2] = __floats2half2_rn(v0, v1);
}

// ---------------- launch --------------------------------------------------------
extern "C" void kernel_launch(void* const* d_in, const int* in_sizes, int n_in,
                              void* d_out, int out_size) {
    const float* x       = (const float*)d_in[0];
    const float* Wq      = (const float*)d_in[1];
    const float* Wk      = (const float*)d_in[2];
    const float* Wv      = (const float*)d_in[3];
    const float* Wb      = (const float*)d_in[4];
    const float* Wa      = (const float*)d_in[5];
    const float* Wg      = (const float*)d_in[6];
    const float* Wo      = (const float*)d_in[7];
    const float* conv_q  = (const float*)d_in[8];
    const float* conv_k  = (const float*)d_in[9];
    const float* conv_v  = (const float*)d_in[10];
    const float* A_log   = (const float*)d_in[11];
    const float* dt_bias = (const float*)d_in[12];
    const float* gnw     = (const float*)d_in[13];
    float* out = (float*)d_out;

    float *pre, *qn, *kn;
    __half2 *Wch, *Woh, *xh, *onh;
    cudaGetSymbolAddress((void**)&pre, g_pre);
    cudaGetSymbolAddress((void**)&Wch, g_Wch);
    cudaGetSymbolAddress((void**)&Woh, g_Woh);
    cudaGetSymbolAddress((void**)&xh,  g_xh);
    cudaGetSymbolAddress((void**)&onh, g_onh);
    cudaGetSymbolAddress((void**)&qn,  g_qn);
    cudaGetSymbolAddress((void**)&kn,  g_kn);

    cudaFuncSetAttribute(gemm_h, cudaFuncAttributeMaxDynamicSharedMemorySize, SMEM_GEMMH);
    cudaFuncSetAttribute(delta_kernel, cudaFuncAttributeMaxDynamicSharedMemorySize, DELTA_SMEM);

    const int M = Bsz * Tn;   // 8192

    pack_w_kernel<<<1024, 256>>>(Wq, Wk, Wv, Wg);
    pack_wo_kernel<<<512, 256>>>(Wo);
    pack_x_kernel<<<1024, 256>>>(x);

    // big projection GEMM: pre[8192,6144] = xh @ Wch
    gemm_h<<<dim3(NPRE / TN, M / TM), 128, SMEM_GEMMH>>>(xh, Wch, pre, M, NPRE, Dm / 2);

    betag_gemm_kernel<<<M / BGR, 256>>>(x, Wb, Wa, A_log, dt_bias);

    convnorm_qk4_kernel<<<Bsz * (Tn / 4) * Hh, DK>>>(conv_q, qn, 0, 0.08838834764831845f);
    convnorm_qk4_kernel<<<Bsz * (Tn / 4) * Hh, DK>>>(conv_k, kn, 1024, 1.0f);
    convsilu_v4_kernel<<<4096, 256>>>(conv_v);

    kk_kernel<<<BH * Tn / 8, 256>>>();

    {
        dim3 grid(BH, DV / DVT);
        delta_kernel<<<grid, 256, DELTA_SMEM>>>();
    }

    gatednorm_kernel<<<Bsz * Tn * Hh, DV / 2>>>(gnw);

    // output GEMM: out[8192,2048] = onh @ Woh
    gemm_h<<<dim3(Dm / TN, M / TM), 128, SMEM_GEMMH>>>(onh, Woh, out, M, Dm, Dm / 2);
}

// round 16
// speedup vs baseline: 1.1182x; 1.0038x over previous
#include <cuda_runtime.h>
#include <cuda_fp16.h>
#include <math.h>
#include <stdint.h>

// Problem constants
#define Bsz 2
#define Tn 4096
#define Dm 2048
#define Hh 8
#define DK 128
#define DV 256
#define Wc 4
#define BH (Bsz*Hh)          // 16
#define QKC (Hh*DK)          // 1024
#define VC  (Hh*DV)          // 2048
#define NPRE 6144            // packed q|k|v|g columns

// ---------------- scratch (device globals; no allocations allowed) -------------
__device__ float   g_pre [(size_t)Bsz*Tn*NPRE];   // packed projections (fp32)
__device__ __half2 g_Wch [(size_t)(Dm/2)*NPRE];   // packed weights, half2 pairs along K
__device__ __half2 g_Woh [(size_t)(Dm/2)*Dm];     // Wo, half2 pairs along K
__device__ __half2 g_xh  [(size_t)Bsz*Tn*(Dm/2)]; // x, half2 pairs along K
__device__ __half2 g_onh [(size_t)Bsz*Tn*(VC/2)]; // gated-norm output, half2 pairs
__device__ float   g_qn  [(size_t)BH*Tn*DK];
__device__ float   g_kn  [(size_t)BH*Tn*DK];
__device__ float   g_vc  [(size_t)BH*Tn*DV];
__device__ float   g_eg  [(size_t)BH*Tn];
__device__ float   g_beta[(size_t)BH*Tn];
__device__ float   g_kk  [(size_t)BH*Tn];         // c_t = k_{t+1} . k_t
__device__ float   g_o   [(size_t)BH*Tn*DV];

__device__ __forceinline__ float siluf(float x) { return x / (1.f + __expf(-x)); }

__device__ __forceinline__ uint32_t smem_u32(const void* p) {
    uint32_t a;
    asm("{ .reg .u64 t; cvta.to.shared.u64 t, %1; cvt.u32.u64 %0, t; }" : "=r"(a) : "l"(p));
    return a;
}

#define CP_ASYNC16(dst, src) \
    asm volatile("cp.async.cg.shared.global [%0], [%1], 16;" \
        :: "r"((uint32_t)(dst)), "l"(src) : "memory")
#define CP_COMMIT() asm volatile("cp.async.commit_group;" ::: "memory")

// ============ fp16 m16n8k16 GEMM, fp32 accum, 4-stage cp.async pipeline ========
#define TM 128
#define TN 128
#define TKc2 16
#define AST2 20
#define BST2 136
#define STG_WORDS (TM*AST2 + TKc2*BST2)    // 4736
#define NST 4
#define SMEM_GEMMH (NST*STG_WORDS*4)       // 75776 bytes

__global__ void __launch_bounds__(128, 2) gemm_h(
    const __half2* __restrict__ A, const __half2* __restrict__ B,
    float* __restrict__ C, int Mtot, int Ntot, int K2tot) {
    extern __shared__ uint32_t sm[];
    const int tid = threadIdx.x, lane = tid & 31, wid = tid >> 5;
    const int wm = (wid & 1) * 64;
    const int wn = (wid >> 1) * 64;
    const int m0 = blockIdx.y * TM, n0 = blockIdx.x * TN;
    const int la3 = lane & 3, l4 = lane >> 2;

    float acc[4][8][4];
#pragma unroll
    for (int mt = 0; mt < 4; mt++)
#pragma unroll
        for (int nt = 0; nt < 8; nt++)
#pragma unroll
            for (int i = 0; i < 4; i++) acc[mt][nt][i] = 0.f;

    const int nch = K2tot / TKc2;

    auto load_stage = [&](int c, int s) {
        uint32_t* sa = sm + s * STG_WORDS;
        uint32_t* sb = sa + TM * AST2;
        const __half2* Ab = A + (size_t)m0 * K2tot + c * TKc2;
        const __half2* Bb = B + (size_t)(c * TKc2) * Ntot + n0;
#pragma unroll
        for (int i = 0; i < 4; i++) {
            int idx = tid + i * 128;
            int r = idx >> 2, cc = idx & 3;
            CP_ASYNC16(smem_u32(sa + r * AST2 + cc * 4), Ab + (size_t)r * K2tot + cc * 4);
        }
#pragma unroll
        for (int i = 0; i < 4; i++) {
            int idx = tid + i * 128;
            int r = idx >> 5, n4 = idx & 31;
            CP_ASYNC16(smem_u32(sb + r * BST2 + n4 * 4), Bb + (size_t)r * Ntot + n4 * 4);
        }
        CP_COMMIT();
    };

    load_stage(0, 0);
    load_stage(1, 1);
    load_stage(2, 2);

    for (int c = 0; c < nch; c++) {
        if (c + 3 <= nch)      asm volatile("cp.async.wait_group 2;" ::: "memory");
        else if (c + 2 == nch) asm volatile("cp.async.wait_group 1;" ::: "memory");
        else                   asm volatile("cp.async.wait_group 0;" ::: "memory");
        __syncthreads();
        if (c + 3 < nch) load_stage(c + 3, (c + 3) % NST);

        const uint32_t* sa = sm + (c % NST) * STG_WORDS;
        const uint32_t* sb = sa + TM * AST2;
#pragma unroll
        for (int ks = 0; ks < 2; ks++) {
            uint32_t a[4][4];
#pragma unroll
            for (int mt = 0; mt < 4; mt++) {
                int mm = wm + mt * 16 + l4;
                int base = mm * AST2 + ks * 8 + la3;
                a[mt][0] = sa[base];
                a[mt][1] = sa[base + 8 * AST2];
                a[mt][2] = sa[base + 4];
                a[mt][3] = sa[base + 8 * AST2 + 4];
            }
            uint32_t b[8][2];
#pragma unroll
            for (int nt = 0; nt < 8; nt++) {
                int nn = wn + nt * 8 + l4;
                b[nt][0] = sb[(ks * 8 + la3) * BST2 + nn];
                b[nt][1] = sb[(ks * 8 + la3 + 4) * BST2 + nn];
            }
#pragma unroll
            for (int mt = 0; mt < 4; mt++)
#pragma unroll
                for (int nt = 0; nt < 8; nt++) {
                    asm volatile(
                        "mma.sync.aligned.m16n8k16.row.col.f32.f16.f16.f32 "
                        "{%0,%1,%2,%3}, {%4,%5,%6,%7}, {%8,%9}, {%0,%1,%2,%3};"
                        : "+f"(acc[mt][nt][0]), "+f"(acc[mt][nt][1]),
                          "+f"(acc[mt][nt][2]), "+f"(acc[mt][nt][3])
                        : "r"(a[mt][0]), "r"(a[mt][1]), "r"(a[mt][2]), "r"(a[mt][3]),
                          "r"(b[nt][0]), "r"(b[nt][1]));
                }
        }
    }

#pragma unroll
    for (int mt = 0; mt < 4; mt++) {
#pragma unroll
        for (int nt = 0; nt < 8; nt++) {
            int row = m0 + wm + mt * 16 + l4;
            int col = n0 + wn + nt * 8 + la3 * 2;
            *reinterpret_cast<float2*>(&C[(size_t)row * Ntot + col]) =
                make_float2(acc[mt][nt][0], acc[mt][nt][1]);
            *reinterpret_cast<float2*>(&C[(size_t)(row + 8) * Ntot + col]) =
                make_float2(acc[mt][nt][2], acc[mt][nt][3]);
        }
    }
}

// ---------------- merged pack: Wq|Wk|Wv|Wg -> g_Wch, Wo -> g_Woh, x -> g_xh -----
__global__ void pack_all_kernel(const float* __restrict__ Wq, const float* __restrict__ Wk,
                                const float* __restrict__ Wv, const float* __restrict__ Wg,
                                const float* __restrict__ Wo, const float* __restrict__ x) {
    const size_t nW  = (size_t)(Dm / 2) * NPRE;        // 6.29M
    const size_t nWo = (size_t)(Dm / 2) * Dm;          // 2.10M
    const size_t nX  = (size_t)Bsz * Tn * Dm / 2;      // 8.39M
    size_t total = nW + nWo + nX;
    for (size_t i = (size_t)blockIdx.x * blockDim.x + threadIdx.x; i < total;
         i += (size_t)gridDim.x * blockDim.x) {
        if (i < nW) {
            int col = (int)(i % NPRE);
            int k2 = (int)(i / NPRE);
            const float* src; int c;
            if (col < 1024)       { src = Wq; c = col;        }
            else if (col < 2048)  { src = Wk; c = col - 1024; }
            else if (col < 4096)  { src = Wv; c = col - 2048; }
            else                  { src = Wg; c = col - 4096; }
            int ncol = (col < 2048) ? 1024 : 2048;
            float v0 = src[(size_t)(2 * k2) * ncol + c];
            float v1 = src[(size_t)(2 * k2 + 1) * ncol + c];
            g_Wch[i] = __floats2half2_rn(v0, v1);
        } else if (i < nW + nWo) {
            size_t j = i - nW;
            int col = (int)(j % Dm);
            int k2 = (int)(j / Dm);
            float v0 = Wo[(size_t)(2 * k2) * Dm + col];
            float v1 = Wo[(size_t)(2 * k2 + 1) * Dm + col];
            g_Woh[j] = __floats2half2_rn(v0, v1);
        } else {
            size_t j = i - nW - nWo;
            float2 v = reinterpret_cast<const float2*>(x)[j];
            g_xh[j] = __floats2half2_rn(v.x, v.y);
        }
    }
}

// ---------------- fused beta/g projection + activations (R12 warp version) -----
__global__ void betag_fused_kernel(const float* __restrict__ x,
                                   const float* __restrict__ Wb, const float* __restrict__ Wa,
                                   const float* __restrict__ A_log,
                                   const float* __restrict__ dt_bias) {
    int wid = threadIdx.x >> 5, lane = threadIdx.x & 31;
    int row = blockIdx.x * 8 + wid;
    if (row >= Bsz * Tn) return;
    const float* xr = x + (size_t)row * Dm;
    float accB[8], accA[8];
#pragma unroll
    for (int h = 0; h < 8; h++) { accB[h] = 0.f; accA[h] = 0.f; }
    for (int k = lane; k < Dm; k += 32) {
        float xv = xr[k];
        const float4* wb = reinterpret_cast<const float4*>(Wb + (size_t)k * 8);
        const float4* wa = reinterpret_cast<const float4*>(Wa + (size_t)k * 8);
        float4 b0 = wb[0], b1 = wb[1], a0 = wa[0], a1 = wa[1];
        accB[0] += xv * b0.x; accB[1] += xv * b0.y; accB[2] += xv * b0.z; accB[3] += xv * b0.w;
        accB[4] += xv * b1.x; accB[5] += xv * b1.y; accB[6] += xv * b1.z; accB[7] += xv * b1.w;
        accA[0] += xv * a0.x; accA[1] += xv * a0.y; accA[2] += xv * a0.z; accA[3] += xv * a0.w;
        accA[4] += xv * a1.x; accA[5] += xv * a1.y; accA[6] += xv * a1.z; accA[7] += xv * a1.w;
    }
#pragma unroll
    for (int h = 0; h < 8; h++) {
#pragma unroll
        for (int m = 16; m; m >>= 1) {
            accB[h] += __shfl_xor_sync(0xffffffffu, accB[h], m);
            accA[h] += __shfl_xor_sync(0xffffffffu, accA[h], m);
        }
    }
    if (lane < 8) {
        int h = lane;
        float beta = 1.f / (1.f + expf(-accB[h]));
        float xg = accA[h] + dt_bias[h];
        float sp = (xg > 20.f) ? xg : log1pf(expf(xg));
        float gg = -expf(A_log[h]) * sp;
        int b = row / Tn, t = row % Tn;
        size_t o = (size_t)(b * Hh + h) * Tn + t;
        g_eg[o] = expf(gg);
        g_beta[o] = beta;
    }
}

// ---------------- merged causal dwconv+silu+l2norm for q AND k ------------------
// blockIdx.y: 0 = q (offset 0, scaled), 1 = k (offset 1024).
__global__ void convnorm_qk4_kernel(const float* __restrict__ conv_q,
                                    const float* __restrict__ conv_k) {
    int h  = blockIdx.x & 7;
    int tq = (blockIdx.x >> 3) & (Tn / 4 - 1);
    int b  = blockIdx.x >> (3 + 10);
    int t0 = tq * 4;
    int c  = h * DK + threadIdx.x;

    int isK = blockIdx.y;
    const float* convw = isK ? conv_k : conv_q;
    float* out = isK ? g_kn : g_qn;
    float scale = isK ? 1.0f : 0.08838834764831845f;
    int off = isK ? 1024 : 0;

    const float* base = g_pre + (size_t)b * Tn * NPRE + off + c;
    float w0 = convw[(size_t)c * Wc + 0];
    float w1 = convw[(size_t)c * Wc + 1];
    float w2 = convw[(size_t)c * Wc + 2];
    float w3 = convw[(size_t)c * Wc + 3];

    float r[7];
#pragma unroll
    for (int i = 0; i < 7; i++) {
        int tt = t0 - 3 + i;
        r[i] = (tt >= 0) ? base[(size_t)tt * NPRE] : 0.f;
    }
    float s[4], ss[4];
#pragma unroll
    for (int j = 0; j < 4; j++) {
        float a = r[j] * w0 + r[j + 1] * w1 + r[j + 2] * w2 + r[j + 3] * w3;
        s[j] = siluf(a);
        ss[j] = s[j] * s[j];
    }
#pragma unroll
    for (int m = 16; m; m >>= 1) {
#pragma unroll
        for (int j = 0; j < 4; j++)
            ss[j] += __shfl_xor_sync(0xffffffffu, ss[j], m);
    }
    __shared__ float wsum[4][4];
    if ((threadIdx.x & 31) == 0) {
        int wd = threadIdx.x >> 5;
#pragma unroll
        for (int j = 0; j < 4; j++) wsum[wd][j] = ss[j];
    }
    __syncthreads();
    size_t ob = ((size_t)(b * Hh + h) * Tn + t0) * DK + threadIdx.x;
#pragma unroll
    for (int j = 0; j < 4; j++) {
        float tot = wsum[0][j] + wsum[1][j] + wsum[2][j] + wsum[3][j];
        out[ob + (size_t)j * DK] = s[j] * rsqrtf(tot + 1e-6f) * scale;
    }
}

// ---------------- causal dwconv + silu for v (4 t's per thread) -----------------
__global__ void convsilu_v4_kernel(const float* __restrict__ convw) {
    size_t total = (size_t)Bsz * (Tn / 4) * VC;
    for (size_t idx = (size_t)blockIdx.x * blockDim.x + threadIdx.x;
         idx < total; idx += (size_t)gridDim.x * blockDim.x) {
        int c  = (int)(idx % VC);
        int tq = (int)((idx / VC) % (Tn / 4));
        int b  = (int)(idx / ((size_t)VC * (Tn / 4)));
        int t0 = tq * 4;
        int h = c >> 8, dv = c & 255;

        const float* base = g_pre + (size_t)b * Tn * NPRE + 2048 + c;
        float w0 = convw[(size_t)c * Wc + 0];
        float w1 = convw[(size_t)c * Wc + 1];
        float w2 = convw[(size_t)c * Wc + 2];
        float w3 = convw[(size_t)c * Wc + 3];

        float r[7];
#pragma unroll
        for (int i = 0; i < 7; i++) {
            int tt = t0 - 3 + i;
            r[i] = (tt >= 0) ? base[(size_t)tt * NPRE] : 0.f;
        }
        size_t ob = ((size_t)(b * Hh + h) * Tn + t0) * DV + dv;
#pragma unroll
        for (int j = 0; j < 4; j++) {
            float a = r[j] * w0 + r[j + 1] * w1 + r[j + 2] * w2 + r[j + 3] * w3;
            g_vc[ob + (size_t)j * DV] = siluf(a);
        }
    }
}

// ---------------- k_{t+1} . k_t dots --------------------------------------------
__global__ void kk_kernel() {
    int wid = threadIdx.x >> 5, lane = threadIdx.x & 31;
    int idx = blockIdx.x * 8 + wid;              // bh*Tn + t
    if (idx >= BH * Tn) return;
    int t = idx & (Tn - 1);
    float s = 0.f;
    if (t + 1 < Tn) {
        const float* k0 = g_kn + (size_t)idx * DK;
        float4 a = reinterpret_cast<const float4*>(k0)[lane];
        float4 b = reinterpret_cast<const float4*>(k0 + DK)[lane];
        s = a.x * b.x + a.y * b.y + a.z * b.z + a.w * b.w;
    }
#pragma unroll
    for (int m = 16; m; m >>= 1) s += __shfl_xor_sync(0xffffffffu, s, m);
    if (lane == 0) g_kk[idx] = s;
}

// ---------------- gated delta-rule recurrence (R12 version) ---------------------
// 256 threads: col = tid>>3 (32 value-cols), sub = tid&7 (16 rows each).
// p_{t+1} = eg_t*(k_{t+1}.S_{t-1}) + (k_{t+1}.k_t)*w_t; o deferred/batched.
#define DVT 32
#define STAGE 32
#define SUBW2 20
#define SKROW 160                  // 8*SUBW2
#define OFF_SK 0
#define OFF_SQ (OFF_SK + (STAGE+1)*SKROW)   // 5280
#define OFF_SV (OFF_SQ + STAGE*SKROW)       // 10400
#define OFF_OP (OFF_SV + STAGE*DVT)         // 11424
#define OFF_EG (OFF_OP + STAGE*256)         // 19616
#define OFF_BT (OFF_EG + STAGE)
#define OFF_CC (OFF_BT + STAGE)
#define DELTA_SMEM ((OFF_CC + STAGE) * 4)   // 78848 bytes

__global__ void __launch_bounds__(256, 1) delta_kernel() {
    extern __shared__ float dsm[];
    float* sK  = dsm + OFF_SK;
    float* sQ  = dsm + OFF_SQ;
    float* sV  = dsm + OFF_SV;
    float* oP  = dsm + OFF_OP;
    float* sEg = dsm + OFF_EG;
    float* sBt = dsm + OFF_BT;
    float* sC  = dsm + OFF_CC;

    int bh = blockIdx.x;
    int vt = blockIdx.y;
    int tid = threadIdx.x;           // 256
    int col = tid >> 3;              // 0..31
    int sub = tid & 7;               // rows [sub*16, sub*16+16)

    const float* kb  = g_kn   + (size_t)bh * Tn * DK;
    const float* qb  = g_qn   + (size_t)bh * Tn * DK;
    const float* vb  = g_vc   + (size_t)bh * Tn * DV;
    const float* egb = g_eg   + (size_t)bh * Tn;
    const float* btb = g_beta + (size_t)bh * Tn;
    const float* ccb = g_kk   + (size_t)bh * Tn;
    float* ob        = g_o    + (size_t)bh * Tn * DV;

    float S[16];
#pragma unroll
    for (int i = 0; i < 16; i++) S[i] = 0.f;
    float E_prev = 0.f, w_prev = 0.f, c_prev = 0.f, eg_prev = 0.f;

    for (int c0 = 0; c0 < Tn; c0 += STAGE) {
        __syncthreads();
#pragma unroll
        for (int l = 0; l < 4; l++) {
            int linear = tid + l * 256;
            int tl = linear >> 5;
            int v4 = linear & 31;
            float4 kv = reinterpret_cast<const float4*>(kb + (size_t)(c0 + tl) * DK)[v4];
            float4 qv = reinterpret_cast<const float4*>(qb + (size_t)(c0 + tl) * DK)[v4];
            int off = (v4 >> 2) * SUBW2 + (v4 & 3) * 4;
            *reinterpret_cast<float4*>(&sK[tl * SKROW + off]) = kv;
            *reinterpret_cast<float4*>(&sQ[tl * SKROW + off]) = qv;
        }
        if (tid < 32) {
            int row = c0 + 32; if (row > Tn - 1) row = Tn - 1;
            float4 kv = reinterpret_cast<const float4*>(kb + (size_t)row * DK)[tid];
            int off = (tid >> 2) * SUBW2 + (tid & 3) * 4;
            *reinterpret_cast<float4*>(&sK[32 * SKROW + off]) = kv;
        }
        {
            int tl = tid >> 3;
            int v4 = tid & 7;
            float4 vv = reinterpret_cast<const float4*>(vb + (size_t)(c0 + tl) * DV + vt * DVT)[v4];
            *reinterpret_cast<float4*>(&sV[tl * DVT + v4 * 4]) = vv;
        }
        if (tid < STAGE) {
            sEg[tid] = egb[c0 + tid];
            sBt[tid] = btb[c0 + tid];
            sC[tid]  = ccb[c0 + tid];
        }
        __syncthreads();

        float4 kq[4];
        {
            const float4* kr = reinterpret_cast<const float4*>(&sK[sub * SUBW2]);
#pragma unroll
            for (int j = 0; j < 4; j++) kq[j] = kr[j];
        }

#pragma unroll 4
        for (int s = 0; s < STAGE; s++) {
            float eg = sEg[s], bt = sBt[s], cc = sC[s];
            float v = sV[s * DVT + col];

            float p = eg_prev * E_prev + c_prev * w_prev;
            float w = bt * (v - eg * p);

            float4 kn[4];
            const float4* krn = reinterpret_cast<const float4*>(&sK[(s + 1) * SKROW + sub * SUBW2]);
#pragma unroll
            for (int j = 0; j < 4; j++) kn[j] = krn[j];

            float e0 = 0.f, e1 = 0.f, e2 = 0.f, e3 = 0.f;
#pragma unroll
            for (int j = 0; j < 4; j++) {
                e0 += kn[j].x * S[4 * j + 0];
                e1 += kn[j].y * S[4 * j + 1];
                e2 += kn[j].z * S[4 * j + 2];
                e3 += kn[j].w * S[4 * j + 3];
            }
            float E = (e0 + e1) + (e2 + e3);
            E += __shfl_xor_sync(0xffffffffu, E, 1);
            E += __shfl_xor_sync(0xffffffffu, E, 2);
            E += __shfl_xor_sync(0xffffffffu, E, 4);

            const float4* qr = reinterpret_cast<const float4*>(&sQ[s * SKROW + sub * SUBW2]);
            float o0 = 0.f, o1 = 0.f, o2 = 0.f, o3 = 0.f;
#pragma unroll
            for (int j = 0; j < 4; j++) {
                float4 qv = qr[j];
                S[4 * j + 0] = eg * S[4 * j + 0] + kq[j].x * w;
                S[4 * j + 1] = eg * S[4 * j + 1] + kq[j].y * w;
                S[4 * j + 2] = eg * S[4 * j + 2] + kq[j].z * w;
                S[4 * j + 3] = eg * S[4 * j + 3] + kq[j].w * w;
                o0 += qv.x * S[4 * j + 0];
                o1 += qv.y * S[4 * j + 1];
                o2 += qv.z * S[4 * j + 2];
                o3 += qv.w * S[4 * j + 3];
            }
            oP[s * 256 + col * 8 + sub] = (o0 + o1) + (o2 + o3);

            E_prev = E; w_prev = w; c_prev = cc; eg_prev = eg;
#pragma unroll
            for (int j = 0; j < 4; j++) kq[j] = kn[j];
        }
        __syncthreads();

#pragma unroll
        for (int r = 0; r < 4; r++) {
            int idx = r * 256 + tid;
            int t = idx >> 5, cl = idx & 31;
            const float* b = &oP[t * 256 + cl * 8];
            float sum = ((b[0] + b[1]) + (b[2] + b[3])) + ((b[4] + b[5]) + (b[6] + b[7]));
            ob[(size_t)(c0 + t) * DV + vt * DVT + cl] = sum;
        }
    }
}

// ---------------- gated RMSNorm + silu(gate), half2 output ---------------------
__global__ void gatednorm_kernel(const float* __restrict__ g_norm_w) {
    int idx = blockIdx.x;
    int h = idx % Hh;
    int t = (idx / Hh) % Tn;
    int b = idx / (Hh * Tn);
    int dv = threadIdx.x * 2;
    size_t obase = ((size_t)(b * Hh + h) * Tn + t) * DV;
    float o0 = g_o[obase + dv];
    float o1 = g_o[obase + dv + 1];
    float ss = o0 * o0 + o1 * o1;
#pragma unroll
    for (int m = 16; m; m >>= 1) ss += __shfl_xor_sync(0xffffffffu, ss, m);
    __shared__ float wsum[4];
    if ((threadIdx.x & 31) == 0) wsum[threadIdx.x >> 5] = ss;
    __syncthreads();
    float tot = wsum[0] + wsum[1] + wsum[2] + wsum[3];
    float r = rsqrtf(tot * (1.f / DV) + 1e-5f);
    size_t gb = ((size_t)(b * Tn + t)) * NPRE + 4096 + h * DV + dv;
    float gt0 = g_pre[gb], gt1 = g_pre[gb + 1];
    float v0 = o0 * r * g_norm_w[dv] * siluf(gt0);
    float v1 = o1 * r * g_norm_w[dv + 1] * siluf(gt1);
    g_onh[((size_t)(b * Tn + t)) * (VC / 2) + (h * DV + dv) / 2] = __floats2half2_rn(v0, v1);
}

// ---------------- launch --------------------------------------------------------
extern "C" void kernel_launch(void* const* d_in, const int* in_sizes, int n_in,
                              void* d_out, int out_size) {
    const float* x       = (const float*)d_in[0];
    const float* Wq      = (const float*)d_in[1];
    const float* Wk      = (const float*)d_in[2];
    const float* Wv      = (const float*)d_in[3];
    const float* Wb      = (const float*)d_in[4];
    const float* Wa      = (const float*)d_in[5];
    const float* Wg      = (const float*)d_in[6];
    const float* Wo      = (const float*)d_in[7];
    const float* conv_q  = (const float*)d_in[8];
    const float* conv_k  = (const float*)d_in[9];
    const float* conv_v  = (const float*)d_in[10];
    const float* A_log   = (const float*)d_in[11];
    const float* dt_bias = (const float*)d_in[12];
    const float* gnw     = (const float*)d_in[13];
    float* out = (float*)d_out;

    float *pre;
    __half2 *Wch, *Woh, *xh, *onh;
    cudaGetSymbolAddress((void**)&pre, g_pre);
    cudaGetSymbolAddress((void**)&Wch, g_Wch);
    cudaGetSymbolAddress((void**)&Woh, g_Woh);
    cudaGetSymbolAddress((void**)&xh,  g_xh);
    cudaGetSymbolAddress((void**)&onh, g_onh);

    cudaFuncSetAttribute(gemm_h, cudaFuncAttributeMaxDynamicSharedMemorySize, SMEM_GEMMH);
    cudaFuncSetAttribute(delta_kernel, cudaFuncAttributeMaxDynamicSharedMemorySize, DELTA_SMEM);

    const int M = Bsz * Tn;   // 8192

    pack_all_kernel<<<2048, 256>>>(Wq, Wk, Wv, Wg, Wo, x);

    // big projection GEMM: pre[8192,6144] = xh @ Wch
    gemm_h<<<dim3(NPRE / TN, M / TM), 128, SMEM_GEMMH>>>(xh, Wch, pre, M, NPRE, Dm / 2);

    betag_fused_kernel<<<M / 8, 256>>>(x, Wb, Wa, A_log, dt_bias);

    convnorm_qk4_kernel<<<dim3(Bsz * (Tn / 4) * Hh, 2), DK>>>(conv_q, conv_k);
    convsilu_v4_kernel<<<4096, 256>>>(conv_v);

    kk_kernel<<<BH * Tn / 8, 256>>>();

    {
        dim3 grid(BH, DV / DVT);
        delta_kernel<<<grid, 256, DELTA_SMEM>>>();
    }

    gatednorm_kernel<<<Bsz * Tn * Hh, DV / 2>>>(gnw);

    // output GEMM: out[8192,2048] = onh @ Woh
    gemm_h<<<dim3(Dm / TN, M / TM), 128, SMEM_GEMMH>>>(onh, Woh, out, M, Dm, Dm / 2);
}

// round 17
// speedup vs baseline: 1.1423x; 1.0216x over previous
#include <cuda_runtime.h>
#include <cuda_fp16.h>
#include <math.h>
#include <stdint.h>

// Problem constants
#define Bsz 2
#define Tn 4096
#define Dm 2048
#define Hh 8
#define DK 128
#define DV 256
#define Wc 4
#define BH (Bsz*Hh)          // 16
#define QKC (Hh*DK)          // 1024
#define VC  (Hh*DV)          // 2048
#define NPRE 6144            // packed q|k|v|g columns

// ---------------- scratch (device globals; no allocations allowed) -------------
__device__ float   g_pre [(size_t)Bsz*Tn*NPRE];   // packed projections (fp32)
__device__ __half2 g_Wch [(size_t)(Dm/2)*NPRE];   // packed weights, half2 pairs along K
__device__ __half2 g_Woh [(size_t)(Dm/2)*Dm];     // Wo, half2 pairs along K
__device__ __half2 g_xh  [(size_t)Bsz*Tn*(Dm/2)]; // x, half2 pairs along K
__device__ __half2 g_onh [(size_t)Bsz*Tn*(VC/2)]; // gated-norm output, half2 pairs
__device__ float   g_qn  [(size_t)BH*Tn*DK];
__device__ float   g_kn  [(size_t)BH*Tn*DK];
__device__ float   g_vc  [(size_t)BH*Tn*DV];
__device__ float   g_eg  [(size_t)BH*Tn];
__device__ float   g_beta[(size_t)BH*Tn];
__device__ float   g_kk  [(size_t)BH*Tn];         // c_t = k_{t+1} . k_t
__device__ float   g_o   [(size_t)BH*Tn*DV];

__device__ __forceinline__ float siluf(float x) { return x / (1.f + __expf(-x)); }

__device__ __forceinline__ uint32_t smem_u32(const void* p) {
    uint32_t a;
    asm("{ .reg .u64 t; cvta.to.shared.u64 t, %1; cvt.u32.u64 %0, t; }" : "=r"(a) : "l"(p));
    return a;
}

#define CP_ASYNC16(dst, src) \
    asm volatile("cp.async.cg.shared.global [%0], [%1], 16;" \
        :: "r"((uint32_t)(dst)), "l"(src) : "memory")
#define CP_ASYNC4(dst, src) \
    asm volatile("cp.async.ca.shared.global [%0], [%1], 4;" \
        :: "r"((uint32_t)(dst)), "l"(src) : "memory")
#define CP_COMMIT() asm volatile("cp.async.commit_group;" ::: "memory")

// ============ fp16 m16n8k16 GEMM, fp32 accum, 4-stage cp.async pipeline ========
#define TM 128
#define TN 128
#define TKc2 16
#define AST2 20
#define BST2 136
#define STG_WORDS (TM*AST2 + TKc2*BST2)    // 4736
#define NST 4
#define SMEM_GEMMH (NST*STG_WORDS*4)       // 75776 bytes

__global__ void __launch_bounds__(128, 2) gemm_h(
    const __half2* __restrict__ A, const __half2* __restrict__ B,
    float* __restrict__ C, int Mtot, int Ntot, int K2tot) {
    extern __shared__ uint32_t sm[];
    const int tid = threadIdx.x, lane = tid & 31, wid = tid >> 5;
    const int wm = (wid & 1) * 64;
    const int wn = (wid >> 1) * 64;
    const int m0 = blockIdx.y * TM, n0 = blockIdx.x * TN;
    const int la3 = lane & 3, l4 = lane >> 2;

    float acc[4][8][4];
#pragma unroll
    for (int mt = 0; mt < 4; mt++)
#pragma unroll
        for (int nt = 0; nt < 8; nt++)
#pragma unroll
            for (int i = 0; i < 4; i++) acc[mt][nt][i] = 0.f;

    const int nch = K2tot / TKc2;

    auto load_stage = [&](int c, int s) {
        uint32_t* sa = sm + s * STG_WORDS;
        uint32_t* sb = sa + TM * AST2;
        const __half2* Ab = A + (size_t)m0 * K2tot + c * TKc2;
        const __half2* Bb = B + (size_t)(c * TKc2) * Ntot + n0;
#pragma unroll
        for (int i = 0; i < 4; i++) {
            int idx = tid + i * 128;
            int r = idx >> 2, cc = idx & 3;
            CP_ASYNC16(smem_u32(sa + r * AST2 + cc * 4), Ab + (size_t)r * K2tot + cc * 4);
        }
#pragma unroll
        for (int i = 0; i < 4; i++) {
            int idx = tid + i * 128;
            int r = idx >> 5, n4 = idx & 31;
            CP_ASYNC16(smem_u32(sb + r * BST2 + n4 * 4), Bb + (size_t)r * Ntot + n4 * 4);
        }
        CP_COMMIT();
    };

    load_stage(0, 0);
    load_stage(1, 1);
    load_stage(2, 2);

    for (int c = 0; c < nch; c++) {
        if (c + 3 <= nch)      asm volatile("cp.async.wait_group 2;" ::: "memory");
        else if (c + 2 == nch) asm volatile("cp.async.wait_group 1;" ::: "memory");
        else                   asm volatile("cp.async.wait_group 0;" ::: "memory");
        __syncthreads();
        if (c + 3 < nch) load_stage(c + 3, (c + 3) % NST);

        const uint32_t* sa = sm + (c % NST) * STG_WORDS;
        const uint32_t* sb = sa + TM * AST2;
#pragma unroll
        for (int ks = 0; ks < 2; ks++) {
            uint32_t a[4][4];
#pragma unroll
            for (int mt = 0; mt < 4; mt++) {
                int mm = wm + mt * 16 + l4;
                int base = mm * AST2 + ks * 8 + la3;
                a[mt][0] = sa[base];
                a[mt][1] = sa[base + 8 * AST2];
                a[mt][2] = sa[base + 4];
                a[mt][3] = sa[base + 8 * AST2 + 4];
            }
            uint32_t b[8][2];
#pragma unroll
            for (int nt = 0; nt < 8; nt++) {
                int nn = wn + nt * 8 + l4;
                b[nt][0] = sb[(ks * 8 + la3) * BST2 + nn];
                b[nt][1] = sb[(ks * 8 + la3 + 4) * BST2 + nn];
            }
#pragma unroll
            for (int mt = 0; mt < 4; mt++)
#pragma unroll
                for (int nt = 0; nt < 8; nt++) {
                    asm volatile(
                        "mma.sync.aligned.m16n8k16.row.col.f32.f16.f16.f32 "
                        "{%0,%1,%2,%3}, {%4,%5,%6,%7}, {%8,%9}, {%0,%1,%2,%3};"
                        : "+f"(acc[mt][nt][0]), "+f"(acc[mt][nt][1]),
                          "+f"(acc[mt][nt][2]), "+f"(acc[mt][nt][3])
                        : "r"(a[mt][0]), "r"(a[mt][1]), "r"(a[mt][2]), "r"(a[mt][3]),
                          "r"(b[nt][0]), "r"(b[nt][1]));
                }
        }
    }

#pragma unroll
    for (int mt = 0; mt < 4; mt++) {
#pragma unroll
        for (int nt = 0; nt < 8; nt++) {
            int row = m0 + wm + mt * 16 + l4;
            int col = n0 + wn + nt * 8 + la3 * 2;
            *reinterpret_cast<float2*>(&C[(size_t)row * Ntot + col]) =
                make_float2(acc[mt][nt][0], acc[mt][nt][1]);
            *reinterpret_cast<float2*>(&C[(size_t)(row + 8) * Ntot + col]) =
                make_float2(acc[mt][nt][2], acc[mt][nt][3]);
        }
    }
}

// ---------------- merged pack: Wq|Wk|Wv|Wg -> g_Wch, Wo -> g_Woh, x -> g_xh -----
__global__ void pack_all_kernel(const float* __restrict__ Wq, const float* __restrict__ Wk,
                                const float* __restrict__ Wv, const float* __restrict__ Wg,
                                const float* __restrict__ Wo, const float* __restrict__ x) {
    const size_t nW  = (size_t)(Dm / 2) * NPRE;
    const size_t nWo = (size_t)(Dm / 2) * Dm;
    const size_t nX  = (size_t)Bsz * Tn * Dm / 2;
    size_t total = nW + nWo + nX;
    for (size_t i = (size_t)blockIdx.x * blockDim.x + threadIdx.x; i < total;
         i += (size_t)gridDim.x * blockDim.x) {
        if (i < nW) {
            int col = (int)(i % NPRE);
            int k2 = (int)(i / NPRE);
            const float* src; int c;
            if (col < 1024)       { src = Wq; c = col;        }
            else if (col < 2048)  { src = Wk; c = col - 1024; }
            else if (col < 4096)  { src = Wv; c = col - 2048; }
            else                  { src = Wg; c = col - 4096; }
            int ncol = (col < 2048) ? 1024 : 2048;
            float v0 = src[(size_t)(2 * k2) * ncol + c];
            float v1 = src[(size_t)(2 * k2 + 1) * ncol + c];
            g_Wch[i] = __floats2half2_rn(v0, v1);
        } else if (i < nW + nWo) {
            size_t j = i - nW;
            int col = (int)(j % Dm);
            int k2 = (int)(j / Dm);
            float v0 = Wo[(size_t)(2 * k2) * Dm + col];
            float v1 = Wo[(size_t)(2 * k2 + 1) * Dm + col];
            g_Woh[j] = __floats2half2_rn(v0, v1);
        } else {
            size_t j = i - nW - nWo;
            float2 v = reinterpret_cast<const float2*>(x)[j];
            g_xh[j] = __floats2half2_rn(v.x, v.y);
        }
    }
}

// ---------------- fused beta/g projection + activations ------------------------
__global__ void betag_fused_kernel(const float* __restrict__ x,
                                   const float* __restrict__ Wb, const float* __restrict__ Wa,
                                   const float* __restrict__ A_log,
                                   const float* __restrict__ dt_bias) {
    int wid = threadIdx.x >> 5, lane = threadIdx.x & 31;
    int row = blockIdx.x * 8 + wid;
    if (row >= Bsz * Tn) return;
    const float* xr = x + (size_t)row * Dm;
    float accB[8], accA[8];
#pragma unroll
    for (int h = 0; h < 8; h++) { accB[h] = 0.f; accA[h] = 0.f; }
    for (int k = lane; k < Dm; k += 32) {
        float xv = xr[k];
        const float4* wb = reinterpret_cast<const float4*>(Wb + (size_t)k * 8);
        const float4* wa = reinterpret_cast<const float4*>(Wa + (size_t)k * 8);
        float4 b0 = wb[0], b1 = wb[1], a0 = wa[0], a1 = wa[1];
        accB[0] += xv * b0.x; accB[1] += xv * b0.y; accB[2] += xv * b0.z; accB[3] += xv * b0.w;
        accB[4] += xv * b1.x; accB[5] += xv * b1.y; accB[6] += xv * b1.z; accB[7] += xv * b1.w;
        accA[0] += xv * a0.x; accA[1] += xv * a0.y; accA[2] += xv * a0.z; accA[3] += xv * a0.w;
        accA[4] += xv * a1.x; accA[5] += xv * a1.y; accA[6] += xv * a1.z; accA[7] += xv * a1.w;
    }
#pragma unroll
    for (int h = 0; h < 8; h++) {
#pragma unroll
        for (int m = 16; m; m >>= 1) {
            accB[h] += __shfl_xor_sync(0xffffffffu, accB[h], m);
            accA[h] += __shfl_xor_sync(0xffffffffu, accA[h], m);
        }
    }
    if (lane < 8) {
        int h = lane;
        float beta = 1.f / (1.f + expf(-accB[h]));
        float xg = accA[h] + dt_bias[h];
        float sp = (xg > 20.f) ? xg : log1pf(expf(xg));
        float gg = -expf(A_log[h]) * sp;
        int b = row / Tn, t = row % Tn;
        size_t o = (size_t)(b * Hh + h) * Tn + t;
        g_eg[o] = expf(gg);
        g_beta[o] = beta;
    }
}

// ---------------- merged causal dwconv+silu+l2norm for q AND k ------------------
__global__ void convnorm_qk4_kernel(const float* __restrict__ conv_q,
                                    const float* __restrict__ conv_k) {
    int h  = blockIdx.x & 7;
    int tq = (blockIdx.x >> 3) & (Tn / 4 - 1);
    int b  = blockIdx.x >> (3 + 10);
    int t0 = tq * 4;
    int c  = h * DK + threadIdx.x;

    int isK = blockIdx.y;
    const float* convw = isK ? conv_k : conv_q;
    float* out = isK ? g_kn : g_qn;
    float scale = isK ? 1.0f : 0.08838834764831845f;
    int off = isK ? 1024 : 0;

    const float* base = g_pre + (size_t)b * Tn * NPRE + off + c;
    float w0 = convw[(size_t)c * Wc + 0];
    float w1 = convw[(size_t)c * Wc + 1];
    float w2 = convw[(size_t)c * Wc + 2];
    float w3 = convw[(size_t)c * Wc + 3];

    float r[7];
#pragma unroll
    for (int i = 0; i < 7; i++) {
        int tt = t0 - 3 + i;
        r[i] = (tt >= 0) ? base[(size_t)tt * NPRE] : 0.f;
    }
    float s[4], ss[4];
#pragma unroll
    for (int j = 0; j < 4; j++) {
        float a = r[j] * w0 + r[j + 1] * w1 + r[j + 2] * w2 + r[j + 3] * w3;
        s[j] = siluf(a);
        ss[j] = s[j] * s[j];
    }
#pragma unroll
    for (int m = 16; m; m >>= 1) {
#pragma unroll
        for (int j = 0; j < 4; j++)
            ss[j] += __shfl_xor_sync(0xffffffffu, ss[j], m);
    }
    __shared__ float wsum[4][4];
    if ((threadIdx.x & 31) == 0) {
        int wd = threadIdx.x >> 5;
#pragma unroll
        for (int j = 0; j < 4; j++) wsum[wd][j] = ss[j];
    }
    __syncthreads();
    size_t ob = ((size_t)(b * Hh + h) * Tn + t0) * DK + threadIdx.x;
#pragma unroll
    for (int j = 0; j < 4; j++) {
        float tot = wsum[0][j] + wsum[1][j] + wsum[2][j] + wsum[3][j];
        out[ob + (size_t)j * DK] = s[j] * rsqrtf(tot + 1e-6f) * scale;
    }
}

// ---------------- causal dwconv + silu for v (4 t's per thread) -----------------
__global__ void convsilu_v4_kernel(const float* __restrict__ convw) {
    size_t total = (size_t)Bsz * (Tn / 4) * VC;
    for (size_t idx = (size_t)blockIdx.x * blockDim.x + threadIdx.x;
         idx < total; idx += (size_t)gridDim.x * blockDim.x) {
        int c  = (int)(idx % VC);
        int tq = (int)((idx / VC) % (Tn / 4));
        int b  = (int)(idx / ((size_t)VC * (Tn / 4)));
        int t0 = tq * 4;
        int h = c >> 8, dv = c & 255;

        const float* base = g_pre + (size_t)b * Tn * NPRE + 2048 + c;
        float w0 = convw[(size_t)c * Wc + 0];
        float w1 = convw[(size_t)c * Wc + 1];
        float w2 = convw[(size_t)c * Wc + 2];
        float w3 = convw[(size_t)c * Wc + 3];

        float r[7];
#pragma unroll
        for (int i = 0; i < 7; i++) {
            int tt = t0 - 3 + i;
            r[i] = (tt >= 0) ? base[(size_t)tt * NPRE] : 0.f;
        }
        size_t ob = ((size_t)(b * Hh + h) * Tn + t0) * DV + dv;
#pragma unroll
        for (int j = 0; j < 4; j++) {
            float a = r[j] * w0 + r[j + 1] * w1 + r[j + 2] * w2 + r[j + 3] * w3;
            g_vc[ob + (size_t)j * DV] = siluf(a);
        }
    }
}

// ---------------- k_{t+1} . k_t dots --------------------------------------------
__global__ void kk_kernel() {
    int wid = threadIdx.x >> 5, lane = threadIdx.x & 31;
    int idx = blockIdx.x * 8 + wid;              // bh*Tn + t
    if (idx >= BH * Tn) return;
    int t = idx & (Tn - 1);
    float s = 0.f;
    if (t + 1 < Tn) {
        const float* k0 = g_kn + (size_t)idx * DK;
        float4 a = reinterpret_cast<const float4*>(k0)[lane];
        float4 b = reinterpret_cast<const float4*>(k0 + DK)[lane];
        s = a.x * b.x + a.y * b.y + a.z * b.z + a.w * b.w;
    }
#pragma unroll
    for (int m = 16; m; m >>= 1) s += __shfl_xor_sync(0xffffffffu, s, m);
    if (lane == 0) g_kk[idx] = s;
}

// ---------------- gated delta-rule recurrence (R12 + double-buffered cp.async) --
// 256 threads: col = tid>>3 (32 value-cols), sub = tid&7 (16 rows each).
// p_{t+1} = eg_t*(k_{t+1}.S_{t-1}) + (k_{t+1}.k_t)*w_t; o deferred/batched.
// Stage loads double-buffered via cp.async: stage i+1 prefetched during compute
// of stage i. Inner loop identical to R12.
#define DVT 32
#define STAGE 32
#define SUBW2 20
#define SKROW 160                    // 8*SUBW2
#define KWORDS ((STAGE+1)*SKROW)     // 5280
#define QWORDS (STAGE*SKROW)         // 5120
#define VWORDS (STAGE*DVT)           // 1024
#define OFF_SK 0
#define OFF_SQ (OFF_SK + 2*KWORDS)          // 10560
#define OFF_SV (OFF_SQ + 2*QWORDS)          // 20800
#define OFF_EG (OFF_SV + 2*VWORDS)          // 22848
#define OFF_BT (OFF_EG + 2*STAGE)           // 22912
#define OFF_CC (OFF_BT + 2*STAGE)           // 22976
#define OFF_OP (OFF_CC + 2*STAGE)           // 23040
#define DELTA_SMEM ((OFF_OP + STAGE*256) * 4)   // 124928 bytes

__global__ void __launch_bounds__(256, 1) delta_kernel() {
    extern __shared__ float dsm[];
    float* oP = dsm + OFF_OP;

    int bh = blockIdx.x;
    int vt = blockIdx.y;
    int tid = threadIdx.x;           // 256
    int col = tid >> 3;              // 0..31
    int sub = tid & 7;               // rows [sub*16, sub*16+16)

    const float* kb  = g_kn   + (size_t)bh * Tn * DK;
    const float* qb  = g_qn   + (size_t)bh * Tn * DK;
    const float* vb  = g_vc   + (size_t)bh * Tn * DV;
    const float* egb = g_eg   + (size_t)bh * Tn;
    const float* btb = g_beta + (size_t)bh * Tn;
    const float* ccb = g_kk   + (size_t)bh * Tn;
    float* ob        = g_o    + (size_t)bh * Tn * DV;

    // async stage loader into buffer bf
    auto load_stage = [&](int c0n, int bf) {
        float* dK = dsm + OFF_SK + bf * KWORDS;
        float* dQ = dsm + OFF_SQ + bf * QWORDS;
        float* dV = dsm + OFF_SV + bf * VWORDS;
#pragma unroll
        for (int l = 0; l < 4; l++) {
            int linear = tid + l * 256;
            int tl = linear >> 5;
            int v4 = linear & 31;
            int off = (v4 >> 2) * SUBW2 + (v4 & 3) * 4;
            CP_ASYNC16(smem_u32(dK + tl * SKROW + off), kb + (size_t)(c0n + tl) * DK + v4 * 4);
            CP_ASYNC16(smem_u32(dQ + tl * SKROW + off), qb + (size_t)(c0n + tl) * DK + v4 * 4);
        }
        if (tid < 32) {
            int row = c0n + 32; if (row > Tn - 1) row = Tn - 1;
            int off = (tid >> 2) * SUBW2 + (tid & 3) * 4;
            CP_ASYNC16(smem_u32(dK + 32 * SKROW + off), kb + (size_t)row * DK + tid * 4);
        }
        {
            int tl = tid >> 3;
            int v4 = tid & 7;
            CP_ASYNC16(smem_u32(dV + tl * DVT + v4 * 4),
                       vb + (size_t)(c0n + tl) * DV + vt * DVT + v4 * 4);
        }
        if (tid < STAGE) {
            CP_ASYNC4(smem_u32(dsm + OFF_EG + bf * STAGE + tid), egb + c0n + tid);
            CP_ASYNC4(smem_u32(dsm + OFF_BT + bf * STAGE + tid), btb + c0n + tid);
            CP_ASYNC4(smem_u32(dsm + OFF_CC + bf * STAGE + tid), ccb + c0n + tid);
        }
        CP_COMMIT();
    };

    float S[16];
#pragma unroll
    for (int i = 0; i < 16; i++) S[i] = 0.f;
    float E_prev = 0.f, w_prev = 0.f, c_prev = 0.f, eg_prev = 0.f;

    const int nstg = Tn / STAGE;     // 128
    load_stage(0, 0);

    for (int ci = 0; ci < nstg; ci++) {
        int bf = ci & 1;
        asm volatile("cp.async.wait_group 0;" ::: "memory");
        __syncthreads();
        if (ci + 1 < nstg) load_stage((ci + 1) * STAGE, bf ^ 1);

        const float* sK  = dsm + OFF_SK + bf * KWORDS;
        const float* sQ  = dsm + OFF_SQ + bf * QWORDS;
        const float* sV  = dsm + OFF_SV + bf * VWORDS;
        const float* sEg = dsm + OFF_EG + bf * STAGE;
        const float* sBt = dsm + OFF_BT + bf * STAGE;
        const float* sC  = dsm + OFF_CC + bf * STAGE;
        int c0 = ci * STAGE;

        float4 kq[4];
        {
            const float4* kr = reinterpret_cast<const float4*>(&sK[sub * SUBW2]);
#pragma unroll
            for (int j = 0; j < 4; j++) kq[j] = kr[j];
        }

#pragma unroll 4
        for (int s = 0; s < STAGE; s++) {
            float eg = sEg[s], bt = sBt[s], cc = sC[s];
            float v = sV[s * DVT + col];

            float p = eg_prev * E_prev + c_prev * w_prev;
            float w = bt * (v - eg * p);

            float4 kn[4];
            const float4* krn = reinterpret_cast<const float4*>(&sK[(s + 1) * SKROW + sub * SUBW2]);
#pragma unroll
            for (int j = 0; j < 4; j++) kn[j] = krn[j];

            float e0 = 0.f, e1 = 0.f, e2 = 0.f, e3 = 0.f;
#pragma unroll
            for (int j = 0; j < 4; j++) {
                e0 += kn[j].x * S[4 * j + 0];
                e1 += kn[j].y * S[4 * j + 1];
                e2 += kn[j].z * S[4 * j + 2];
                e3 += kn[j].w * S[4 * j + 3];
            }
            float E = (e0 + e1) + (e2 + e3);
            E += __shfl_xor_sync(0xffffffffu, E, 1);
            E += __shfl_xor_sync(0xffffffffu, E, 2);
            E += __shfl_xor_sync(0xffffffffu, E, 4);

            const float4* qr = reinterpret_cast<const float4*>(&sQ[s * SKROW + sub * SUBW2]);
            float o0 = 0.f, o1 = 0.f, o2 = 0.f, o3 = 0.f;
#pragma unroll
            for (int j = 0; j < 4; j++) {
                float4 qv = qr[j];
                S[4 * j + 0] = eg * S[4 * j + 0] + kq[j].x * w;
                S[4 * j + 1] = eg * S[4 * j + 1] + kq[j].y * w;
                S[4 * j + 2] = eg * S[4 * j + 2] + kq[j].z * w;
                S[4 * j + 3] = eg * S[4 * j + 3] + kq[j].w * w;
                o0 += qv.x * S[4 * j + 0];
                o1 += qv.y * S[4 * j + 1];
                o2 += qv.z * S[4 * j + 2];
                o3 += qv.w * S[4 * j + 3];
            }
            oP[s * 256 + col * 8 + sub] = (o0 + o1) + (o2 + o3);

            E_prev = E; w_prev = w; c_prev = cc; eg_prev = eg;
#pragma unroll
            for (int j = 0; j < 4; j++) kq[j] = kn[j];
        }
        __syncthreads();

#pragma unroll
        for (int r = 0; r < 4; r++) {
            int idx = r * 256 + tid;
            int t = idx >> 5, cl = idx & 31;
            const float* b = &oP[t * 256 + cl * 8];
            float sum = ((b[0] + b[1]) + (b[2] + b[3])) + ((b[4] + b[5]) + (b[6] + b[7]));
            ob[(size_t)(c0 + t) * DV + vt * DVT + cl] = sum;
        }
    }
}

// ---------------- gated RMSNorm + silu(gate), half2 output ---------------------
__global__ void gatednorm_kernel(const float* __restrict__ g_norm_w) {
    int idx = blockIdx.x;
    int h = idx % Hh;
    int t = (idx / Hh) % Tn;
    int b = idx / (Hh * Tn);
    int dv = threadIdx.x * 2;
    size_t obase = ((size_t)(b * Hh + h) * Tn + t) * DV;
    float o0 = g_o[obase + dv];
    float o1 = g_o[obase + dv + 1];
    float ss = o0 * o0 + o1 * o1;
#pragma unroll
    for (int m = 16; m; m >>= 1) ss += __shfl_xor_sync(0xffffffffu, ss, m);
    __shared__ float wsum[4];
    if ((threadIdx.x & 31) == 0) wsum[threadIdx.x >> 5] = ss;
    __syncthreads();
    float tot = wsum[0] + wsum[1] + wsum[2] + wsum[3];
    float r = rsqrtf(tot * (1.f / DV) + 1e-5f);
    size_t gb = ((size_t)(b * Tn + t)) * NPRE + 4096 + h * DV + dv;
    float gt0 = g_pre[gb], gt1 = g_pre[gb + 1];
    float v0 = o0 * r * g_norm_w[dv] * siluf(gt0);
    float v1 = o1 * r * g_norm_w[dv + 1] * siluf(gt1);
    g_onh[((size_t)(b * Tn + t)) * (VC / 2) + (h * DV + dv) / 2] = __floats2half2_rn(v0, v1);
}

// ---------------- launch --------------------------------------------------------
extern "C" void kernel_launch(void* const* d_in, const int* in_sizes, int n_in,
                              void* d_out, int out_size) {
    const float* x       = (const float*)d_in[0];
    const float* Wq      = (const float*)d_in[1];
    const float* Wk      = (const float*)d_in[2];
    const float* Wv      = (const float*)d_in[3];
    const float* Wb      = (const float*)d_in[4];
    const float* Wa      = (const float*)d_in[5];
    const float* Wg      = (const float*)d_in[6];
    const float* Wo      = (const float*)d_in[7];
    const float* conv_q  = (const float*)d_in[8];
    const float* conv_k  = (const float*)d_in[9];
    const float* conv_v  = (const float*)d_in[10];
    const float* A_log   = (const float*)d_in[11];
    const float* dt_bias = (const float*)d_in[12];
    const float* gnw     = (const float*)d_in[13];
    float* out = (float*)d_out;

    float *pre;
    __half2 *Wch, *Woh, *xh, *onh;
    cudaGetSymbolAddress((void**)&pre, g_pre);
    cudaGetSymbolAddress((void**)&Wch, g_Wch);
    cudaGetSymbolAddress((void**)&Woh, g_Woh);
    cudaGetSymbolAddress((void**)&xh,  g_xh);
    cudaGetSymbolAddress((void**)&onh, g_onh);

    cudaFuncSetAttribute(gemm_h, cudaFuncAttributeMaxDynamicSharedMemorySize, SMEM_GEMMH);
    cudaFuncSetAttribute(delta_kernel, cudaFuncAttributeMaxDynamicSharedMemorySize, DELTA_SMEM);

    const int M = Bsz * Tn;   // 8192

    pack_all_kernel<<<2048, 256>>>(Wq, Wk, Wv, Wg, Wo, x);

    // big projection GEMM: pre[8192,6144] = xh @ Wch
    gemm_h<<<dim3(NPRE / TN, M / TM), 128, SMEM_GEMMH>>>(xh, Wch, pre, M, NPRE, Dm / 2);

    betag_fused_kernel<<<M / 8, 256>>>(x, Wb, Wa, A_log, dt_bias);

    convnorm_qk4_kernel<<<dim3(Bsz * (Tn / 4) * Hh, 2), DK>>>(conv_q, conv_k);
    convsilu_v4_kernel<<<4096, 256>>>(conv_v);

    kk_kernel<<<BH * Tn / 8, 256>>>();

    {
        dim3 grid(BH, DV / DVT);
        delta_kernel<<<grid, 256, DELTA_SMEM>>>();
    }

    gatednorm_kernel<<<Bsz * Tn * Hh, DV / 2>>>(gnw);

    // output GEMM: out[8192,2048] = onh @ Woh
    gemm_h<<<dim3(Dm / TN, M / TM), 128, SMEM_GEMMH>>>(onh, Woh, out, M, Dm, Dm / 2);
}